// round 1
// baseline (speedup 1.0000x reference)
#include <cuda_runtime.h>
#include <math.h>

#define BB 2
#define SS 2048
#define DD 1024
#define HH 16
#define DK 64
#define NT (BB*SS)   // 4096 tokens

// ---- scratch (static device globals; no allocations) ----
__device__ float g_Q[(size_t)NT*DD];
__device__ float g_K[(size_t)NT*DD];
__device__ float g_V[(size_t)NT*DD];
__device__ float g_ctx[(size_t)NT*DD];
__device__ float g_pre[(size_t)NT*DD];
__device__ float g_scores[(size_t)BB*HH*SS*SS];
__device__ float g_dummy_out[(size_t)NT*DD];   // fallback LN target

// ============================================================
// C[M,N] = A[M,K] @ B[N,K]^T   (row-major A and B)
// BM=128, BN=64, BK=16, 256 threads, 8x4 per thread.
// Requires M%128==0, N%64==0, K%16==0.
// ============================================================
__global__ void gemm_nt_kernel(const float* __restrict__ A,
                               const float* __restrict__ Bm,
                               float* __restrict__ C,
                               int M, int N, int K)
{
    __shared__ float As[16][129];
    __shared__ float Bs[16][65];
    const int t  = threadIdx.x;
    const int tx = t & 15;
    const int ty = t >> 4;
    const int lk = t & 15;     // k within tile
    const int lr = t >> 4;     // row group
    const int i0 = blockIdx.y * 128;
    const int j0 = blockIdx.x * 64;

    float acc[8][4];
#pragma unroll
    for (int i = 0; i < 8; i++)
#pragma unroll
        for (int j = 0; j < 4; j++) acc[i][j] = 0.f;

    for (int k0 = 0; k0 < K; k0 += 16) {
#pragma unroll
        for (int q = 0; q < 8; q++)
            As[lk][lr + 16*q] = A[(size_t)(i0 + lr + 16*q)*K + k0 + lk];
#pragma unroll
        for (int q = 0; q < 4; q++)
            Bs[lk][lr + 16*q] = Bm[(size_t)(j0 + lr + 16*q)*K + k0 + lk];
        __syncthreads();
#pragma unroll
        for (int kk = 0; kk < 16; kk++) {
            float a[8], b[4];
#pragma unroll
            for (int ii = 0; ii < 8; ii++) a[ii] = As[kk][ty*8 + ii];
#pragma unroll
            for (int jj = 0; jj < 4; jj++) b[jj] = Bs[kk][tx*4 + jj];
#pragma unroll
            for (int ii = 0; ii < 8; ii++)
#pragma unroll
                for (int jj = 0; jj < 4; jj++)
                    acc[ii][jj] = fmaf(a[ii], b[jj], acc[ii][jj]);
        }
        __syncthreads();
    }
#pragma unroll
    for (int ii = 0; ii < 8; ii++) {
        const int i = i0 + ty*8 + ii;
#pragma unroll
        for (int jj = 0; jj < 4; jj++)
            C[(size_t)i*N + j0 + tx*4 + jj] = acc[ii][jj];
    }
}

// ============================================================
// scores[bh,i,j] = (Q[b,i,h,:] . K[b,j,h,:]) / 8, masked -> -1e9
// 64x64 tile per block, K=64 fully in smem. mask is int32.
// ============================================================
__global__ void scores_kernel(const int* __restrict__ mask)
{
    const int bh = blockIdx.z;
    const int b  = bh >> 4;
    const int h  = bh & 15;
    const int i0 = blockIdx.y * 64;
    const int j0 = blockIdx.x * 64;

    __shared__ float Qs[64][65];   // [k][i]
    __shared__ float Ks[64][65];   // [k][j]

    const int t  = threadIdx.x;
    const int lk = t & 63;
    const int lr = t >> 6;         // 0..3
    const float* Qb = g_Q + (size_t)b*SS*DD + h*DK;
    const float* Kb = g_K + (size_t)b*SS*DD + h*DK;

#pragma unroll
    for (int q = 0; q < 16; q++) {
        const int r = lr + 4*q;
        Qs[lk][r] = Qb[(size_t)(i0 + r)*DD + lk];
        Ks[lk][r] = Kb[(size_t)(j0 + r)*DD + lk];
    }
    __syncthreads();

    const int tx = t & 15, ty = t >> 4;
    float acc[4][4];
#pragma unroll
    for (int i = 0; i < 4; i++)
#pragma unroll
        for (int j = 0; j < 4; j++) acc[i][j] = 0.f;

#pragma unroll 16
    for (int kk = 0; kk < 64; kk++) {
        float a[4], bb[4];
#pragma unroll
        for (int ii = 0; ii < 4; ii++) a[ii]  = Qs[kk][ty*4 + ii];
#pragma unroll
        for (int jj = 0; jj < 4; jj++) bb[jj] = Ks[kk][tx*4 + jj];
#pragma unroll
        for (int ii = 0; ii < 4; ii++)
#pragma unroll
            for (int jj = 0; jj < 4; jj++)
                acc[ii][jj] = fmaf(a[ii], bb[jj], acc[ii][jj]);
    }

    float* srow = g_scores + (size_t)bh*SS*SS;
#pragma unroll
    for (int ii = 0; ii < 4; ii++) {
        const int i = i0 + ty*4 + ii;
        const int j = j0 + tx*4;
        const int4 m4 = *(const int4*)(mask + ((size_t)b*SS + i)*SS + j);
        float4 v;
        v.x = m4.x ? -1e9f : acc[ii][0]*0.125f;
        v.y = m4.y ? -1e9f : acc[ii][1]*0.125f;
        v.z = m4.z ? -1e9f : acc[ii][2]*0.125f;
        v.w = m4.w ? -1e9f : acc[ii][3]*0.125f;
        *(float4*)(srow + (size_t)i*SS + j) = v;
    }
}

// ============================================================
// softmax over rows of length SS=2048. 256 threads, 8 elems each.
// ============================================================
__global__ void softmax_kernel(const float* __restrict__ sc,
                               float* __restrict__ attn)
{
    const size_t base = (size_t)blockIdx.x * SS;
    const int t = threadIdx.x;
    __shared__ float redm[8];
    __shared__ float reds[8];

    float v[8];
#pragma unroll
    for (int j = 0; j < 8; j++) v[j] = sc[base + t + 256*j];

    float m = v[0];
#pragma unroll
    for (int j = 1; j < 8; j++) m = fmaxf(m, v[j]);
#pragma unroll
    for (int o = 16; o > 0; o >>= 1) m = fmaxf(m, __shfl_xor_sync(0xffffffffu, m, o));
    if ((t & 31) == 0) redm[t >> 5] = m;
    __syncthreads();
    m = redm[0];
#pragma unroll
    for (int w = 1; w < 8; w++) m = fmaxf(m, redm[w]);

    float s = 0.f;
#pragma unroll
    for (int j = 0; j < 8; j++) { v[j] = __expf(v[j] - m); s += v[j]; }
#pragma unroll
    for (int o = 16; o > 0; o >>= 1) s += __shfl_xor_sync(0xffffffffu, s, o);
    if ((t & 31) == 0) reds[t >> 5] = s;
    __syncthreads();
    s = reds[0];
#pragma unroll
    for (int w = 1; w < 8; w++) s += reds[w];

    const float inv = 1.0f / s;
#pragma unroll
    for (int j = 0; j < 8; j++) attn[base + t + 256*j] = v[j]*inv;
}

// ============================================================
// ctx[b,i,h*64+d] = sum_k attn[bh,i,k] * V[b,k,h*64+d]
// 64 rows x 64 cols (full head dim) per block, K tiled by 64.
// ============================================================
__global__ void ctx_kernel(const float* __restrict__ attn)
{
    const int bh = blockIdx.y;
    const int b  = bh >> 4;
    const int h  = bh & 15;
    const int i0 = blockIdx.x * 64;

    __shared__ float As[64][65];   // [i][k]
    __shared__ float Vs[64][65];   // [k][d]

    const int t  = threadIdx.x;
    const int lc = t & 63;
    const int lr = t >> 6;
    const float* arow = attn + ((size_t)bh*SS + i0)*SS;
    const float* Vb   = g_V  + (size_t)b*SS*DD + h*DK;

    const int tx = t & 15, ty = t >> 4;
    float acc[4][4];
#pragma unroll
    for (int i = 0; i < 4; i++)
#pragma unroll
        for (int j = 0; j < 4; j++) acc[i][j] = 0.f;

    for (int k0 = 0; k0 < SS; k0 += 64) {
#pragma unroll
        for (int q = 0; q < 16; q++) {
            const int r = lr + 4*q;
            As[r][lc] = arow[(size_t)r*SS + k0 + lc];
            Vs[r][lc] = Vb[(size_t)(k0 + r)*DD + lc];
        }
        __syncthreads();
#pragma unroll 16
        for (int kk = 0; kk < 64; kk++) {
            float a[4], bb[4];
#pragma unroll
            for (int ii = 0; ii < 4; ii++) a[ii]  = As[ty*4 + ii][kk];
#pragma unroll
            for (int jj = 0; jj < 4; jj++) bb[jj] = Vs[kk][tx*4 + jj];
#pragma unroll
            for (int ii = 0; ii < 4; ii++)
#pragma unroll
                for (int jj = 0; jj < 4; jj++)
                    acc[ii][jj] = fmaf(a[ii], bb[jj], acc[ii][jj]);
        }
        __syncthreads();
    }
#pragma unroll
    for (int ii = 0; ii < 4; ii++) {
        const int i = i0 + ty*4 + ii;
#pragma unroll
        for (int jj = 0; jj < 4; jj++)
            g_ctx[((size_t)b*SS + i)*DD + h*DK + tx*4 + jj] = acc[ii][jj];
    }
}

// ============================================================
// out = LayerNorm(pre + residual), gamma=1 beta=0, eps=1e-5
// one block per token, 256 threads, 4 elems each (DD=1024).
// ============================================================
__global__ void ln_kernel(const float* __restrict__ resid,
                          float* __restrict__ out)
{
    const size_t base = (size_t)blockIdx.x * DD;
    const int t = threadIdx.x;
    __shared__ float red1[8];
    __shared__ float red2[8];

    float v[4];
    float s = 0.f;
#pragma unroll
    for (int j = 0; j < 4; j++) {
        v[j] = g_pre[base + t + 256*j] + resid[base + t + 256*j];
        s += v[j];
    }
#pragma unroll
    for (int o = 16; o > 0; o >>= 1) s += __shfl_xor_sync(0xffffffffu, s, o);
    if ((t & 31) == 0) red1[t >> 5] = s;
    __syncthreads();
    s = red1[0];
#pragma unroll
    for (int w = 1; w < 8; w++) s += red1[w];
    const float mu = s * (1.0f / DD);

    float sq = 0.f;
#pragma unroll
    for (int j = 0; j < 4; j++) { const float d = v[j] - mu; sq += d*d; }
#pragma unroll
    for (int o = 16; o > 0; o >>= 1) sq += __shfl_xor_sync(0xffffffffu, sq, o);
    if ((t & 31) == 0) red2[t >> 5] = sq;
    __syncthreads();
    sq = red2[0];
#pragma unroll
    for (int w = 1; w < 8; w++) sq += red2[w];
    const float inv = rsqrtf(sq * (1.0f / DD) + 1e-5f);

#pragma unroll
    for (int j = 0; j < 4; j++) out[base + t + 256*j] = (v[j] - mu) * inv;
}

// ============================================================
extern "C" void kernel_launch(void* const* d_in, const int* in_sizes, int n_in,
                              void* d_out, int out_size)
{
    const float* inQ  = (const float*)d_in[0];
    const float* inK  = (const float*)d_in[1];
    const float* inV  = (const float*)d_in[2];
    const int*   mask = (const int*)  d_in[3];
    const float* WQ   = (const float*)d_in[4];
    const float* WK   = (const float*)d_in[5];
    const float* WV   = (const float*)d_in[6];
    const float* Wfc  = (const float*)d_in[7];
    float* out = (float*)d_out;

    float *pQ, *pK, *pV, *pctx, *ppre, *psc, *pdmy;
    cudaGetSymbolAddress((void**)&pQ,   g_Q);
    cudaGetSymbolAddress((void**)&pK,   g_K);
    cudaGetSymbolAddress((void**)&pV,   g_V);
    cudaGetSymbolAddress((void**)&pctx, g_ctx);
    cudaGetSymbolAddress((void**)&ppre, g_pre);
    cudaGetSymbolAddress((void**)&psc,  g_scores);
    cudaGetSymbolAddress((void**)&pdmy, g_dummy_out);

    const long long OUT_E  = (long long)NT * DD;               // 4,194,304
    const long long ATTN_E = (long long)BB * HH * SS * SS;     // 134,217,728

    float* out_dst  = out;
    float* attn_dst = psc;                    // default: keep attn in scratch
    if ((long long)out_size >= OUT_E + ATTN_E) {
        attn_dst = out + OUT_E;               // tuple (out, attn) concatenated
    } else if ((long long)out_size == ATTN_E) {
        attn_dst = out;                       // attn-only output
        out_dst  = pdmy;
    }

    const dim3 blk(256);

    // projections: y = x @ W^T
    gemm_nt_kernel<<<dim3(DD/64, NT/128), blk>>>(inQ, WQ, pQ, NT, DD, DD);
    gemm_nt_kernel<<<dim3(DD/64, NT/128), blk>>>(inK, WK, pK, NT, DD, DD);
    gemm_nt_kernel<<<dim3(DD/64, NT/128), blk>>>(inV, WV, pV, NT, DD, DD);

    // scores + mask
    scores_kernel<<<dim3(SS/64, SS/64, BB*HH), blk>>>(mask);

    // softmax (writes attn to its final home)
    softmax_kernel<<<(unsigned)(BB*HH*SS), blk>>>(psc, attn_dst);

    // context = attn @ V
    ctx_kernel<<<dim3(SS/64, BB*HH), blk>>>(attn_dst);

    // output projection
    gemm_nt_kernel<<<dim3(DD/64, NT/128), blk>>>(pctx, Wfc, ppre, NT, DD, DD);

    // residual + layernorm
    ln_kernel<<<(unsigned)NT, blk>>>(inQ, out_dst);
}

// round 2
// speedup vs baseline: 1.4290x; 1.4290x over previous
#include <cuda_runtime.h>
#include <math.h>

#define BB 2
#define SS 2048
#define DD 1024
#define HH 16
#define DK 64
#define NT (BB*SS)   // 4096 tokens
#define PADW 132

typedef unsigned long long ull;

// ---- scratch (static device globals; no allocations) ----
__device__ float g_Q[(size_t)NT*DD];
__device__ float g_K[(size_t)NT*DD];
__device__ float g_V[(size_t)NT*DD];
__device__ float g_ctx[(size_t)NT*DD];
__device__ float g_pre[(size_t)NT*DD];
__device__ float g_scores[(size_t)BB*HH*SS*SS];
__device__ float g_dummy_out[(size_t)NT*DD];

// ---- packed fp32x2 helpers (sm_103a FFMA2) ----
__device__ __forceinline__ ull pk2(float x, float y) {
    ull r;
    asm("mov.b64 %0, {%1, %2};" : "=l"(r)
        : "r"(__float_as_uint(x)), "r"(__float_as_uint(y)));
    return r;
}
__device__ __forceinline__ ull dup2(float x) { return pk2(x, x); }
__device__ __forceinline__ void fma2(ull& d, ull a, ull b) {
    asm("fma.rn.f32x2 %0, %1, %2, %0;" : "+l"(d) : "l"(a), "l"(b));
}
__device__ __forceinline__ float2 up2(ull v) {
    unsigned lo, hi;
    asm("mov.b64 {%0, %1}, %2;" : "=r"(lo), "=r"(hi) : "l"(v));
    return make_float2(__uint_as_float(lo), __uint_as_float(hi));
}

// ============================================================
// C[M,N] = A[M,K] @ B[N,K]^T.  128x128 tile, BK=16, 256 thr,
// 8x8 per thread, double-buffered, FFMA2 inner loop.
// M%128==0, N%128==0, K%16==0.
// ============================================================
__global__ __launch_bounds__(256)
void gemm_nt128(const float* __restrict__ A, const float* __restrict__ B,
                float* __restrict__ C, int M, int N, int K)
{
    __shared__ float As[2][16][PADW];
    __shared__ float Bs[2][16][PADW];
    const int t = threadIdx.x;
    const int lane = t & 31, warp = t >> 5;
    const int wm = warp >> 1, wn = warp & 1;    // 4x2 warp grid
    const int tm = lane >> 3, tn = lane & 7;    // 4x8 in warp (32x64 tile)
    const int i0 = blockIdx.y * 128, j0 = blockIdx.x * 128;
    const int lrow = t >> 2;          // 0..63
    const int lkc  = (t & 3) * 4;     // 0,4,8,12

    const float* Ap = A + (size_t)(i0 + lrow) * K + lkc;
    const float* Bp = B + (size_t)(j0 + lrow) * K + lkc;

    ull acc[2][4][2][2];
#pragma unroll
    for (int a = 0; a < 2; a++)
#pragma unroll
        for (int b = 0; b < 4; b++)
#pragma unroll
            for (int c = 0; c < 2; c++)
#pragma unroll
                for (int d = 0; d < 2; d++) acc[a][b][c][d] = 0ull;

    // prologue
    {
        float4 a0 = *(const float4*)(Ap);
        float4 a1 = *(const float4*)(Ap + (size_t)64 * K);
        float4 b0 = *(const float4*)(Bp);
        float4 b1 = *(const float4*)(Bp + (size_t)64 * K);
        As[0][lkc+0][lrow] = a0.x; As[0][lkc+1][lrow] = a0.y;
        As[0][lkc+2][lrow] = a0.z; As[0][lkc+3][lrow] = a0.w;
        As[0][lkc+0][lrow+64] = a1.x; As[0][lkc+1][lrow+64] = a1.y;
        As[0][lkc+2][lrow+64] = a1.z; As[0][lkc+3][lrow+64] = a1.w;
        Bs[0][lkc+0][lrow] = b0.x; Bs[0][lkc+1][lrow] = b0.y;
        Bs[0][lkc+2][lrow] = b0.z; Bs[0][lkc+3][lrow] = b0.w;
        Bs[0][lkc+0][lrow+64] = b1.x; Bs[0][lkc+1][lrow+64] = b1.y;
        Bs[0][lkc+2][lrow+64] = b1.z; Bs[0][lkc+3][lrow+64] = b1.w;
    }
    __syncthreads();

    int buf = 0;
    for (int k0 = 0; k0 < K; k0 += 16) {
        float4 na0, na1, nb0, nb1;
        const bool more = (k0 + 16 < K);
        if (more) {
            na0 = *(const float4*)(Ap + k0 + 16);
            na1 = *(const float4*)(Ap + (size_t)64 * K + k0 + 16);
            nb0 = *(const float4*)(Bp + k0 + 16);
            nb1 = *(const float4*)(Bp + (size_t)64 * K + k0 + 16);
        }
#pragma unroll
        for (int kk = 0; kk < 16; kk++) {
            const float4 a0 = *(const float4*)&As[buf][kk][wm*32 + tm*4];
            const float4 a1 = *(const float4*)&As[buf][kk][wm*32 + 16 + tm*4];
            const float4 b0 = *(const float4*)&Bs[buf][kk][wn*64 + tn*4];
            const float4 b1 = *(const float4*)&Bs[buf][kk][wn*64 + 32 + tn*4];
            ull bp[2][2] = {{pk2(b0.x,b0.y), pk2(b0.z,b0.w)},
                            {pk2(b1.x,b1.y), pk2(b1.z,b1.w)}};
            float av[2][4] = {{a0.x,a0.y,a0.z,a0.w},{a1.x,a1.y,a1.z,a1.w}};
#pragma unroll
            for (int ri = 0; ri < 2; ri++)
#pragma unroll
                for (int ii = 0; ii < 4; ii++) {
                    ull ad = dup2(av[ri][ii]);
#pragma unroll
                    for (int rj = 0; rj < 2; rj++)
#pragma unroll
                        for (int pj = 0; pj < 2; pj++)
                            fma2(acc[ri][ii][rj][pj], ad, bp[rj][pj]);
                }
        }
        if (more) {
            const int nb = buf ^ 1;
            As[nb][lkc+0][lrow] = na0.x; As[nb][lkc+1][lrow] = na0.y;
            As[nb][lkc+2][lrow] = na0.z; As[nb][lkc+3][lrow] = na0.w;
            As[nb][lkc+0][lrow+64] = na1.x; As[nb][lkc+1][lrow+64] = na1.y;
            As[nb][lkc+2][lrow+64] = na1.z; As[nb][lkc+3][lrow+64] = na1.w;
            Bs[nb][lkc+0][lrow] = nb0.x; Bs[nb][lkc+1][lrow] = nb0.y;
            Bs[nb][lkc+2][lrow] = nb0.z; Bs[nb][lkc+3][lrow] = nb0.w;
            Bs[nb][lkc+0][lrow+64] = nb1.x; Bs[nb][lkc+1][lrow+64] = nb1.y;
            Bs[nb][lkc+2][lrow+64] = nb1.z; Bs[nb][lkc+3][lrow+64] = nb1.w;
        }
        __syncthreads();
        buf ^= 1;
    }

#pragma unroll
    for (int ri = 0; ri < 2; ri++)
#pragma unroll
        for (int ii = 0; ii < 4; ii++) {
            const int i = i0 + wm*32 + ri*16 + tm*4 + ii;
#pragma unroll
            for (int rj = 0; rj < 2; rj++) {
                float2 p0 = up2(acc[ri][ii][rj][0]);
                float2 p1 = up2(acc[ri][ii][rj][1]);
                float4 v = make_float4(p0.x, p0.y, p1.x, p1.y);
                *(float4*)&C[(size_t)i*N + j0 + wn*64 + rj*32 + tn*4] = v;
            }
        }
}

// ============================================================
// scores: 128x128 tile of (Q.K^T)/8 with mask, K=64 per head.
// ============================================================
__global__ __launch_bounds__(256)
void scores128(const int* __restrict__ mask)
{
    __shared__ float As[2][16][PADW];
    __shared__ float Bs[2][16][PADW];
    const int bh = blockIdx.z;
    const int b = bh >> 4, h = bh & 15;
    const int t = threadIdx.x;
    const int lane = t & 31, warp = t >> 5;
    const int wm = warp >> 1, wn = warp & 1;
    const int tm = lane >> 3, tn = lane & 7;
    const int i0 = blockIdx.y * 128, j0 = blockIdx.x * 128;
    const int lrow = t >> 2;
    const int lkc  = (t & 3) * 4;

    const float* Ap = g_Q + (size_t)b*SS*DD + (size_t)(i0 + lrow)*DD + h*DK + lkc;
    const float* Bp = g_K + (size_t)b*SS*DD + (size_t)(j0 + lrow)*DD + h*DK + lkc;

    ull acc[2][4][2][2];
#pragma unroll
    for (int a = 0; a < 2; a++)
#pragma unroll
        for (int c = 0; c < 4; c++)
#pragma unroll
            for (int d = 0; d < 2; d++)
#pragma unroll
                for (int e = 0; e < 2; e++) acc[a][c][d][e] = 0ull;

    {
        float4 a0 = *(const float4*)(Ap);
        float4 a1 = *(const float4*)(Ap + (size_t)64 * DD);
        float4 b0 = *(const float4*)(Bp);
        float4 b1 = *(const float4*)(Bp + (size_t)64 * DD);
        As[0][lkc+0][lrow] = a0.x; As[0][lkc+1][lrow] = a0.y;
        As[0][lkc+2][lrow] = a0.z; As[0][lkc+3][lrow] = a0.w;
        As[0][lkc+0][lrow+64] = a1.x; As[0][lkc+1][lrow+64] = a1.y;
        As[0][lkc+2][lrow+64] = a1.z; As[0][lkc+3][lrow+64] = a1.w;
        Bs[0][lkc+0][lrow] = b0.x; Bs[0][lkc+1][lrow] = b0.y;
        Bs[0][lkc+2][lrow] = b0.z; Bs[0][lkc+3][lrow] = b0.w;
        Bs[0][lkc+0][lrow+64] = b1.x; Bs[0][lkc+1][lrow+64] = b1.y;
        Bs[0][lkc+2][lrow+64] = b1.z; Bs[0][lkc+3][lrow+64] = b1.w;
    }
    __syncthreads();

    int buf = 0;
    for (int k0 = 0; k0 < DK; k0 += 16) {
        float4 na0, na1, nb0, nb1;
        const bool more = (k0 + 16 < DK);
        if (more) {
            na0 = *(const float4*)(Ap + k0 + 16);
            na1 = *(const float4*)(Ap + (size_t)64 * DD + k0 + 16);
            nb0 = *(const float4*)(Bp + k0 + 16);
            nb1 = *(const float4*)(Bp + (size_t)64 * DD + k0 + 16);
        }
#pragma unroll
        for (int kk = 0; kk < 16; kk++) {
            const float4 a0 = *(const float4*)&As[buf][kk][wm*32 + tm*4];
            const float4 a1 = *(const float4*)&As[buf][kk][wm*32 + 16 + tm*4];
            const float4 b0 = *(const float4*)&Bs[buf][kk][wn*64 + tn*4];
            const float4 b1 = *(const float4*)&Bs[buf][kk][wn*64 + 32 + tn*4];
            ull bp[2][2] = {{pk2(b0.x,b0.y), pk2(b0.z,b0.w)},
                            {pk2(b1.x,b1.y), pk2(b1.z,b1.w)}};
            float av[2][4] = {{a0.x,a0.y,a0.z,a0.w},{a1.x,a1.y,a1.z,a1.w}};
#pragma unroll
            for (int ri = 0; ri < 2; ri++)
#pragma unroll
                for (int ii = 0; ii < 4; ii++) {
                    ull ad = dup2(av[ri][ii]);
#pragma unroll
                    for (int rj = 0; rj < 2; rj++)
#pragma unroll
                        for (int pj = 0; pj < 2; pj++)
                            fma2(acc[ri][ii][rj][pj], ad, bp[rj][pj]);
                }
        }
        if (more) {
            const int nb = buf ^ 1;
            As[nb][lkc+0][lrow] = na0.x; As[nb][lkc+1][lrow] = na0.y;
            As[nb][lkc+2][lrow] = na0.z; As[nb][lkc+3][lrow] = na0.w;
            As[nb][lkc+0][lrow+64] = na1.x; As[nb][lkc+1][lrow+64] = na1.y;
            As[nb][lkc+2][lrow+64] = na1.z; As[nb][lkc+3][lrow+64] = na1.w;
            Bs[nb][lkc+0][lrow] = nb0.x; Bs[nb][lkc+1][lrow] = nb0.y;
            Bs[nb][lkc+2][lrow] = nb0.z; Bs[nb][lkc+3][lrow] = nb0.w;
            Bs[nb][lkc+0][lrow+64] = nb1.x; Bs[nb][lkc+1][lrow+64] = nb1.y;
            Bs[nb][lkc+2][lrow+64] = nb1.z; Bs[nb][lkc+3][lrow+64] = nb1.w;
        }
        __syncthreads();
        buf ^= 1;
    }

    float* srow = g_scores + (size_t)bh*SS*SS;
#pragma unroll
    for (int ri = 0; ri < 2; ri++)
#pragma unroll
        for (int ii = 0; ii < 4; ii++) {
            const int i = i0 + wm*32 + ri*16 + tm*4 + ii;
#pragma unroll
            for (int rj = 0; rj < 2; rj++) {
                const int j = j0 + wn*64 + rj*32 + tn*4;
                float2 p0 = up2(acc[ri][ii][rj][0]);
                float2 p1 = up2(acc[ri][ii][rj][1]);
                const int4 m4 = *(const int4*)(mask + ((size_t)b*SS + i)*SS + j);
                float4 v;
                v.x = m4.x ? -1e9f : p0.x * 0.125f;
                v.y = m4.y ? -1e9f : p0.y * 0.125f;
                v.z = m4.z ? -1e9f : p1.x * 0.125f;
                v.w = m4.w ? -1e9f : p1.y * 0.125f;
                *(float4*)(srow + (size_t)i*SS + j) = v;
            }
        }
}

// ============================================================
// softmax over rows of length SS=2048, vectorized.
// ============================================================
__global__ void softmax_kernel(const float* __restrict__ sc,
                               float* __restrict__ attn)
{
    const size_t base = (size_t)blockIdx.x * SS;
    const int t = threadIdx.x;
    __shared__ float redm[8];
    __shared__ float reds[8];

    float4 v0 = *(const float4*)(sc + base + t*4);
    float4 v1 = *(const float4*)(sc + base + 1024 + t*4);

    float m = fmaxf(fmaxf(fmaxf(v0.x, v0.y), fmaxf(v0.z, v0.w)),
                    fmaxf(fmaxf(v1.x, v1.y), fmaxf(v1.z, v1.w)));
#pragma unroll
    for (int o = 16; o > 0; o >>= 1) m = fmaxf(m, __shfl_xor_sync(0xffffffffu, m, o));
    if ((t & 31) == 0) redm[t >> 5] = m;
    __syncthreads();
    m = redm[0];
#pragma unroll
    for (int w = 1; w < 8; w++) m = fmaxf(m, redm[w]);

    v0.x = __expf(v0.x - m); v0.y = __expf(v0.y - m);
    v0.z = __expf(v0.z - m); v0.w = __expf(v0.w - m);
    v1.x = __expf(v1.x - m); v1.y = __expf(v1.y - m);
    v1.z = __expf(v1.z - m); v1.w = __expf(v1.w - m);
    float s = (v0.x + v0.y) + (v0.z + v0.w) + (v1.x + v1.y) + (v1.z + v1.w);
#pragma unroll
    for (int o = 16; o > 0; o >>= 1) s += __shfl_xor_sync(0xffffffffu, s, o);
    if ((t & 31) == 0) reds[t >> 5] = s;
    __syncthreads();
    s = reds[0];
#pragma unroll
    for (int w = 1; w < 8; w++) s += reds[w];

    const float inv = 1.0f / s;
    v0.x *= inv; v0.y *= inv; v0.z *= inv; v0.w *= inv;
    v1.x *= inv; v1.y *= inv; v1.z *= inv; v1.w *= inv;
    *(float4*)(attn + base + t*4) = v0;
    *(float4*)(attn + base + 1024 + t*4) = v1;
}

// ============================================================
// ctx: per (b,h): C[128 x 64] tile = attn[128 x S] @ V[S x 64]
// BK=16, 256 threads, warp grid 4x2 (warp tile 32x32), 8x4/thr.
// ============================================================
__global__ __launch_bounds__(256)
void ctx128(const float* __restrict__ attn)
{
    __shared__ float As[2][16][PADW];
    __shared__ float Vs[2][16][64];
    const int bh = blockIdx.y;
    const int b = bh >> 4, h = bh & 15;
    const int i0 = blockIdx.x * 128;
    const int t = threadIdx.x;
    const int lane = t & 31, warp = t >> 5;
    const int wm = warp >> 1, wn = warp & 1;
    const int tm = lane >> 3, tn = lane & 7;
    const int lrow = t >> 2;
    const int lkc  = (t & 3) * 4;
    const int vrow = t >> 4;          // 0..15
    const int vnc  = (t & 15) * 4;    // 0..60

    const float* Ap = attn + ((size_t)bh*SS + i0 + lrow)*SS + lkc;
    const float* Vp = g_V + (size_t)b*SS*DD + h*DK + (size_t)vrow*DD + vnc;

    ull acc[2][4][2];
#pragma unroll
    for (int a = 0; a < 2; a++)
#pragma unroll
        for (int c = 0; c < 4; c++)
#pragma unroll
            for (int d = 0; d < 2; d++) acc[a][c][d] = 0ull;

    {
        float4 a0 = *(const float4*)(Ap);
        float4 a1 = *(const float4*)(Ap + (size_t)64*SS);
        float4 vv = *(const float4*)(Vp);
        As[0][lkc+0][lrow] = a0.x; As[0][lkc+1][lrow] = a0.y;
        As[0][lkc+2][lrow] = a0.z; As[0][lkc+3][lrow] = a0.w;
        As[0][lkc+0][lrow+64] = a1.x; As[0][lkc+1][lrow+64] = a1.y;
        As[0][lkc+2][lrow+64] = a1.z; As[0][lkc+3][lrow+64] = a1.w;
        *(float4*)&Vs[0][vrow][vnc] = vv;
    }
    __syncthreads();

    int buf = 0;
    for (int k0 = 0; k0 < SS; k0 += 16) {
        float4 na0, na1, nvv;
        const bool more = (k0 + 16 < SS);
        if (more) {
            na0 = *(const float4*)(Ap + k0 + 16);
            na1 = *(const float4*)(Ap + (size_t)64*SS + k0 + 16);
            nvv = *(const float4*)(Vp + (size_t)(k0 + 16)*DD);
        }
#pragma unroll
        for (int kk = 0; kk < 16; kk++) {
            const float4 a0 = *(const float4*)&As[buf][kk][wm*32 + tm*4];
            const float4 a1 = *(const float4*)&As[buf][kk][wm*32 + 16 + tm*4];
            const float4 bv = *(const float4*)&Vs[buf][kk][wn*32 + tn*4];
            ull bp[2] = {pk2(bv.x, bv.y), pk2(bv.z, bv.w)};
            float av[2][4] = {{a0.x,a0.y,a0.z,a0.w},{a1.x,a1.y,a1.z,a1.w}};
#pragma unroll
            for (int ri = 0; ri < 2; ri++)
#pragma unroll
                for (int ii = 0; ii < 4; ii++) {
                    ull ad = dup2(av[ri][ii]);
                    fma2(acc[ri][ii][0], ad, bp[0]);
                    fma2(acc[ri][ii][1], ad, bp[1]);
                }
        }
        if (more) {
            const int nb = buf ^ 1;
            As[nb][lkc+0][lrow] = na0.x; As[nb][lkc+1][lrow] = na0.y;
            As[nb][lkc+2][lrow] = na0.z; As[nb][lkc+3][lrow] = na0.w;
            As[nb][lkc+0][lrow+64] = na1.x; As[nb][lkc+1][lrow+64] = na1.y;
            As[nb][lkc+2][lrow+64] = na1.z; As[nb][lkc+3][lrow+64] = na1.w;
            *(float4*)&Vs[nb][vrow][vnc] = nvv;
        }
        __syncthreads();
        buf ^= 1;
    }

#pragma unroll
    for (int ri = 0; ri < 2; ri++)
#pragma unroll
        for (int ii = 0; ii < 4; ii++) {
            const int i = i0 + wm*32 + ri*16 + tm*4 + ii;
            float2 p0 = up2(acc[ri][ii][0]);
            float2 p1 = up2(acc[ri][ii][1]);
            float4 v = make_float4(p0.x, p0.y, p1.x, p1.y);
            *(float4*)&g_ctx[((size_t)b*SS + i)*DD + h*DK + wn*32 + tn*4] = v;
        }
}

// ============================================================
// out = LayerNorm(pre + residual)
// ============================================================
__global__ void ln_kernel(const float* __restrict__ resid,
                          float* __restrict__ out)
{
    const size_t base = (size_t)blockIdx.x * DD;
    const int t = threadIdx.x;
    __shared__ float red1[8];
    __shared__ float red2[8];

    float v[4];
    float s = 0.f;
#pragma unroll
    for (int j = 0; j < 4; j++) {
        v[j] = g_pre[base + t + 256*j] + resid[base + t + 256*j];
        s += v[j];
    }
#pragma unroll
    for (int o = 16; o > 0; o >>= 1) s += __shfl_xor_sync(0xffffffffu, s, o);
    if ((t & 31) == 0) red1[t >> 5] = s;
    __syncthreads();
    s = red1[0];
#pragma unroll
    for (int w = 1; w < 8; w++) s += red1[w];
    const float mu = s * (1.0f / DD);

    float sq = 0.f;
#pragma unroll
    for (int j = 0; j < 4; j++) { const float d = v[j] - mu; sq += d*d; }
#pragma unroll
    for (int o = 16; o > 0; o >>= 1) sq += __shfl_xor_sync(0xffffffffu, sq, o);
    if ((t & 31) == 0) red2[t >> 5] = sq;
    __syncthreads();
    sq = red2[0];
#pragma unroll
    for (int w = 1; w < 8; w++) sq += red2[w];
    const float inv = rsqrtf(sq * (1.0f / DD) + 1e-5f);

#pragma unroll
    for (int j = 0; j < 4; j++) out[base + t + 256*j] = (v[j] - mu) * inv;
}

// ============================================================
extern "C" void kernel_launch(void* const* d_in, const int* in_sizes, int n_in,
                              void* d_out, int out_size)
{
    const float* inQ  = (const float*)d_in[0];
    const float* inK  = (const float*)d_in[1];
    const float* inV  = (const float*)d_in[2];
    const int*   mask = (const int*)  d_in[3];
    const float* WQ   = (const float*)d_in[4];
    const float* WK   = (const float*)d_in[5];
    const float* WV   = (const float*)d_in[6];
    const float* Wfc  = (const float*)d_in[7];
    float* out = (float*)d_out;

    float *pQ, *pK, *pV, *pctx, *ppre, *psc, *pdmy;
    cudaGetSymbolAddress((void**)&pQ,   g_Q);
    cudaGetSymbolAddress((void**)&pK,   g_K);
    cudaGetSymbolAddress((void**)&pV,   g_V);
    cudaGetSymbolAddress((void**)&pctx, g_ctx);
    cudaGetSymbolAddress((void**)&ppre, g_pre);
    cudaGetSymbolAddress((void**)&psc,  g_scores);
    cudaGetSymbolAddress((void**)&pdmy, g_dummy_out);

    const long long OUT_E  = (long long)NT * DD;
    const long long ATTN_E = (long long)BB * HH * SS * SS;

    float* out_dst  = out;
    float* attn_dst = psc;
    if ((long long)out_size >= OUT_E + ATTN_E) {
        attn_dst = out + OUT_E;
    } else if ((long long)out_size == ATTN_E) {
        attn_dst = out;
        out_dst  = pdmy;
    }

    const dim3 blk(256);

    gemm_nt128<<<dim3(DD/128, NT/128), blk>>>(inQ, WQ, pQ, NT, DD, DD);
    gemm_nt128<<<dim3(DD/128, NT/128), blk>>>(inK, WK, pK, NT, DD, DD);
    gemm_nt128<<<dim3(DD/128, NT/128), blk>>>(inV, WV, pV, NT, DD, DD);

    scores128<<<dim3(SS/128, SS/128, BB*HH), blk>>>(mask);

    softmax_kernel<<<(unsigned)(BB*HH*SS), blk>>>(psc, attn_dst);

    ctx128<<<dim3(SS/128, BB*HH), blk>>>(attn_dst);

    gemm_nt128<<<dim3(DD/128, NT/128), blk>>>(pctx, Wfc, ppre, NT, DD, DD);

    ln_kernel<<<(unsigned)NT, blk>>>(inQ, out_dst);
}

// round 3
// speedup vs baseline: 1.5295x; 1.0703x over previous
#include <cuda_runtime.h>
#include <math.h>

#define BB 2
#define SS 2048
#define DD 1024
#define HH 16
#define DK 64
#define NT (BB*SS)   // 4096 tokens
#define PADW 132

typedef unsigned long long ull;

// ---- scratch (static device globals; no allocations) ----
__device__ float g_Q[(size_t)NT*DD];
__device__ float g_K[(size_t)NT*DD];
__device__ float g_V[(size_t)NT*DD];
__device__ float g_ctx[(size_t)NT*DD];
__device__ float g_pre[(size_t)NT*DD];
__device__ float g_scores[(size_t)BB*HH*SS*SS];
__device__ float g_dummy_out[(size_t)NT*DD];

// ---- packed fp32x2 helpers (sm_103a FFMA2) ----
__device__ __forceinline__ ull pk2(float x, float y) {
    ull r;
    asm("mov.b64 %0, {%1, %2};" : "=l"(r)
        : "r"(__float_as_uint(x)), "r"(__float_as_uint(y)));
    return r;
}
__device__ __forceinline__ ull dup2(float x) { return pk2(x, x); }
__device__ __forceinline__ void fma2(ull& d, ull a, ull b) {
    asm("fma.rn.f32x2 %0, %1, %2, %0;" : "+l"(d) : "l"(a), "l"(b));
}
__device__ __forceinline__ float2 up2(ull v) {
    unsigned lo, hi;
    asm("mov.b64 {%0, %1}, %2;" : "=r"(lo), "=r"(hi) : "l"(v));
    return make_float2(__uint_as_float(lo), __uint_as_float(hi));
}

// ============================================================
// C[M,N] = A[M,K] @ B[N,K]^T.  128x128 tile, BK=16, 256 thr,
// 8x8 per thread, double-buffered, FFMA2 inner loop.
// Reg-capped to 128 => 2 CTAs/SM.
// ============================================================
__global__ __launch_bounds__(256, 2)
void gemm_nt128(const float* __restrict__ A, const float* __restrict__ B,
                float* __restrict__ C, int M, int N, int K)
{
    __shared__ float As[2][16][PADW];
    __shared__ float Bs[2][16][PADW];
    const int t = threadIdx.x;
    const int lane = t & 31, warp = t >> 5;
    const int wm = warp >> 1, wn = warp & 1;    // 4x2 warp grid
    const int tm = lane >> 3, tn = lane & 7;    // 4x8 in warp (32x64 tile)
    const int i0 = blockIdx.y * 128, j0 = blockIdx.x * 128;
    const int lrow = t >> 2;          // 0..63
    const int lkc  = (t & 3) * 4;     // 0,4,8,12

    const float* Ap = A + (size_t)(i0 + lrow) * K + lkc;
    const float* Bp = B + (size_t)(j0 + lrow) * K + lkc;

    ull acc[2][4][2][2];
#pragma unroll
    for (int a = 0; a < 2; a++)
#pragma unroll
        for (int b = 0; b < 4; b++)
#pragma unroll
            for (int c = 0; c < 2; c++)
#pragma unroll
                for (int d = 0; d < 2; d++) acc[a][b][c][d] = 0ull;

    // prologue
    {
        float4 a0 = *(const float4*)(Ap);
        float4 a1 = *(const float4*)(Ap + (size_t)64 * K);
        float4 b0 = *(const float4*)(Bp);
        float4 b1 = *(const float4*)(Bp + (size_t)64 * K);
        As[0][lkc+0][lrow] = a0.x; As[0][lkc+1][lrow] = a0.y;
        As[0][lkc+2][lrow] = a0.z; As[0][lkc+3][lrow] = a0.w;
        As[0][lkc+0][lrow+64] = a1.x; As[0][lkc+1][lrow+64] = a1.y;
        As[0][lkc+2][lrow+64] = a1.z; As[0][lkc+3][lrow+64] = a1.w;
        Bs[0][lkc+0][lrow] = b0.x; Bs[0][lkc+1][lrow] = b0.y;
        Bs[0][lkc+2][lrow] = b0.z; Bs[0][lkc+3][lrow] = b0.w;
        Bs[0][lkc+0][lrow+64] = b1.x; Bs[0][lkc+1][lrow+64] = b1.y;
        Bs[0][lkc+2][lrow+64] = b1.z; Bs[0][lkc+3][lrow+64] = b1.w;
    }
    __syncthreads();

    int buf = 0;
    for (int k0 = 0; k0 < K; k0 += 16) {
        float4 na0, na1, nb0, nb1;
        const bool more = (k0 + 16 < K);
        if (more) {
            na0 = *(const float4*)(Ap + k0 + 16);
            na1 = *(const float4*)(Ap + (size_t)64 * K + k0 + 16);
            nb0 = *(const float4*)(Bp + k0 + 16);
            nb1 = *(const float4*)(Bp + (size_t)64 * K + k0 + 16);
        }
#pragma unroll
        for (int kk = 0; kk < 16; kk++) {
            const float4 a0 = *(const float4*)&As[buf][kk][wm*32 + tm*4];
            const float4 a1 = *(const float4*)&As[buf][kk][wm*32 + 16 + tm*4];
            const float4 b0 = *(const float4*)&Bs[buf][kk][wn*64 + tn*4];
            const float4 b1 = *(const float4*)&Bs[buf][kk][wn*64 + 32 + tn*4];
            ull bp[2][2] = {{pk2(b0.x,b0.y), pk2(b0.z,b0.w)},
                            {pk2(b1.x,b1.y), pk2(b1.z,b1.w)}};
            float av[2][4] = {{a0.x,a0.y,a0.z,a0.w},{a1.x,a1.y,a1.z,a1.w}};
#pragma unroll
            for (int ri = 0; ri < 2; ri++)
#pragma unroll
                for (int ii = 0; ii < 4; ii++) {
                    ull ad = dup2(av[ri][ii]);
#pragma unroll
                    for (int rj = 0; rj < 2; rj++)
#pragma unroll
                        for (int pj = 0; pj < 2; pj++)
                            fma2(acc[ri][ii][rj][pj], ad, bp[rj][pj]);
                }
        }
        if (more) {
            const int nb = buf ^ 1;
            As[nb][lkc+0][lrow] = na0.x; As[nb][lkc+1][lrow] = na0.y;
            As[nb][lkc+2][lrow] = na0.z; As[nb][lkc+3][lrow] = na0.w;
            As[nb][lkc+0][lrow+64] = na1.x; As[nb][lkc+1][lrow+64] = na1.y;
            As[nb][lkc+2][lrow+64] = na1.z; As[nb][lkc+3][lrow+64] = na1.w;
            Bs[nb][lkc+0][lrow] = nb0.x; Bs[nb][lkc+1][lrow] = nb0.y;
            Bs[nb][lkc+2][lrow] = nb0.z; Bs[nb][lkc+3][lrow] = nb0.w;
            Bs[nb][lkc+0][lrow+64] = nb1.x; Bs[nb][lkc+1][lrow+64] = nb1.y;
            Bs[nb][lkc+2][lrow+64] = nb1.z; Bs[nb][lkc+3][lrow+64] = nb1.w;
        }
        __syncthreads();
        buf ^= 1;
    }

#pragma unroll
    for (int ri = 0; ri < 2; ri++)
#pragma unroll
        for (int ii = 0; ii < 4; ii++) {
            const int i = i0 + wm*32 + ri*16 + tm*4 + ii;
#pragma unroll
            for (int rj = 0; rj < 2; rj++) {
                float2 p0 = up2(acc[ri][ii][rj][0]);
                float2 p1 = up2(acc[ri][ii][rj][1]);
                float4 v = make_float4(p0.x, p0.y, p1.x, p1.y);
                *(float4*)&C[(size_t)i*N + j0 + wn*64 + rj*32 + tn*4] = v;
            }
        }
}

// ============================================================
// scores: 128x128 tile of (Q.K^T)/8 with mask, K=64 per head.
// ============================================================
__global__ __launch_bounds__(256, 2)
void scores128(const int* __restrict__ mask)
{
    __shared__ float As[2][16][PADW];
    __shared__ float Bs[2][16][PADW];
    const int bh = blockIdx.z;
    const int b = bh >> 4, h = bh & 15;
    const int t = threadIdx.x;
    const int lane = t & 31, warp = t >> 5;
    const int wm = warp >> 1, wn = warp & 1;
    const int tm = lane >> 3, tn = lane & 7;
    const int i0 = blockIdx.y * 128, j0 = blockIdx.x * 128;
    const int lrow = t >> 2;
    const int lkc  = (t & 3) * 4;

    const float* Ap = g_Q + (size_t)b*SS*DD + (size_t)(i0 + lrow)*DD + h*DK + lkc;
    const float* Bp = g_K + (size_t)b*SS*DD + (size_t)(j0 + lrow)*DD + h*DK + lkc;

    ull acc[2][4][2][2];
#pragma unroll
    for (int a = 0; a < 2; a++)
#pragma unroll
        for (int c = 0; c < 4; c++)
#pragma unroll
            for (int d = 0; d < 2; d++)
#pragma unroll
                for (int e = 0; e < 2; e++) acc[a][c][d][e] = 0ull;

    {
        float4 a0 = *(const float4*)(Ap);
        float4 a1 = *(const float4*)(Ap + (size_t)64 * DD);
        float4 b0 = *(const float4*)(Bp);
        float4 b1 = *(const float4*)(Bp + (size_t)64 * DD);
        As[0][lkc+0][lrow] = a0.x; As[0][lkc+1][lrow] = a0.y;
        As[0][lkc+2][lrow] = a0.z; As[0][lkc+3][lrow] = a0.w;
        As[0][lkc+0][lrow+64] = a1.x; As[0][lkc+1][lrow+64] = a1.y;
        As[0][lkc+2][lrow+64] = a1.z; As[0][lkc+3][lrow+64] = a1.w;
        Bs[0][lkc+0][lrow] = b0.x; Bs[0][lkc+1][lrow] = b0.y;
        Bs[0][lkc+2][lrow] = b0.z; Bs[0][lkc+3][lrow] = b0.w;
        Bs[0][lkc+0][lrow+64] = b1.x; Bs[0][lkc+1][lrow+64] = b1.y;
        Bs[0][lkc+2][lrow+64] = b1.z; Bs[0][lkc+3][lrow+64] = b1.w;
    }
    __syncthreads();

    int buf = 0;
    for (int k0 = 0; k0 < DK; k0 += 16) {
        float4 na0, na1, nb0, nb1;
        const bool more = (k0 + 16 < DK);
        if (more) {
            na0 = *(const float4*)(Ap + k0 + 16);
            na1 = *(const float4*)(Ap + (size_t)64 * DD + k0 + 16);
            nb0 = *(const float4*)(Bp + k0 + 16);
            nb1 = *(const float4*)(Bp + (size_t)64 * DD + k0 + 16);
        }
#pragma unroll
        for (int kk = 0; kk < 16; kk++) {
            const float4 a0 = *(const float4*)&As[buf][kk][wm*32 + tm*4];
            const float4 a1 = *(const float4*)&As[buf][kk][wm*32 + 16 + tm*4];
            const float4 b0 = *(const float4*)&Bs[buf][kk][wn*64 + tn*4];
            const float4 b1 = *(const float4*)&Bs[buf][kk][wn*64 + 32 + tn*4];
            ull bp[2][2] = {{pk2(b0.x,b0.y), pk2(b0.z,b0.w)},
                            {pk2(b1.x,b1.y), pk2(b1.z,b1.w)}};
            float av[2][4] = {{a0.x,a0.y,a0.z,a0.w},{a1.x,a1.y,a1.z,a1.w}};
#pragma unroll
            for (int ri = 0; ri < 2; ri++)
#pragma unroll
                for (int ii = 0; ii < 4; ii++) {
                    ull ad = dup2(av[ri][ii]);
#pragma unroll
                    for (int rj = 0; rj < 2; rj++)
#pragma unroll
                        for (int pj = 0; pj < 2; pj++)
                            fma2(acc[ri][ii][rj][pj], ad, bp[rj][pj]);
                }
        }
        if (more) {
            const int nb = buf ^ 1;
            As[nb][lkc+0][lrow] = na0.x; As[nb][lkc+1][lrow] = na0.y;
            As[nb][lkc+2][lrow] = na0.z; As[nb][lkc+3][lrow] = na0.w;
            As[nb][lkc+0][lrow+64] = na1.x; As[nb][lkc+1][lrow+64] = na1.y;
            As[nb][lkc+2][lrow+64] = na1.z; As[nb][lkc+3][lrow+64] = na1.w;
            Bs[nb][lkc+0][lrow] = nb0.x; Bs[nb][lkc+1][lrow] = nb0.y;
            Bs[nb][lkc+2][lrow] = nb0.z; Bs[nb][lkc+3][lrow] = nb0.w;
            Bs[nb][lkc+0][lrow+64] = nb1.x; Bs[nb][lkc+1][lrow+64] = nb1.y;
            Bs[nb][lkc+2][lrow+64] = nb1.z; Bs[nb][lkc+3][lrow+64] = nb1.w;
        }
        __syncthreads();
        buf ^= 1;
    }

    float* srow = g_scores + (size_t)bh*SS*SS;
#pragma unroll
    for (int ri = 0; ri < 2; ri++)
#pragma unroll
        for (int ii = 0; ii < 4; ii++) {
            const int i = i0 + wm*32 + ri*16 + tm*4 + ii;
#pragma unroll
            for (int rj = 0; rj < 2; rj++) {
                const int j = j0 + wn*64 + rj*32 + tn*4;
                float2 p0 = up2(acc[ri][ii][rj][0]);
                float2 p1 = up2(acc[ri][ii][rj][1]);
                const int4 m4 = *(const int4*)(mask + ((size_t)b*SS + i)*SS + j);
                float4 v;
                v.x = m4.x ? -1e9f : p0.x * 0.125f;
                v.y = m4.y ? -1e9f : p0.y * 0.125f;
                v.z = m4.z ? -1e9f : p1.x * 0.125f;
                v.w = m4.w ? -1e9f : p1.y * 0.125f;
                *(float4*)(srow + (size_t)i*SS + j) = v;
            }
        }
}

// ============================================================
// softmax over rows of length SS=2048, vectorized.
// ============================================================
__global__ void softmax_kernel(const float* __restrict__ sc,
                               float* __restrict__ attn)
{
    const size_t base = (size_t)blockIdx.x * SS;
    const int t = threadIdx.x;
    __shared__ float redm[8];
    __shared__ float reds[8];

    float4 v0 = *(const float4*)(sc + base + t*4);
    float4 v1 = *(const float4*)(sc + base + 1024 + t*4);

    float m = fmaxf(fmaxf(fmaxf(v0.x, v0.y), fmaxf(v0.z, v0.w)),
                    fmaxf(fmaxf(v1.x, v1.y), fmaxf(v1.z, v1.w)));
#pragma unroll
    for (int o = 16; o > 0; o >>= 1) m = fmaxf(m, __shfl_xor_sync(0xffffffffu, m, o));
    if ((t & 31) == 0) redm[t >> 5] = m;
    __syncthreads();
    m = redm[0];
#pragma unroll
    for (int w = 1; w < 8; w++) m = fmaxf(m, redm[w]);

    v0.x = __expf(v0.x - m); v0.y = __expf(v0.y - m);
    v0.z = __expf(v0.z - m); v0.w = __expf(v0.w - m);
    v1.x = __expf(v1.x - m); v1.y = __expf(v1.y - m);
    v1.z = __expf(v1.z - m); v1.w = __expf(v1.w - m);
    float s = (v0.x + v0.y) + (v0.z + v0.w) + (v1.x + v1.y) + (v1.z + v1.w);
#pragma unroll
    for (int o = 16; o > 0; o >>= 1) s += __shfl_xor_sync(0xffffffffu, s, o);
    if ((t & 31) == 0) reds[t >> 5] = s;
    __syncthreads();
    s = reds[0];
#pragma unroll
    for (int w = 1; w < 8; w++) s += reds[w];

    const float inv = 1.0f / s;
    v0.x *= inv; v0.y *= inv; v0.z *= inv; v0.w *= inv;
    v1.x *= inv; v1.y *= inv; v1.z *= inv; v1.w *= inv;
    *(float4*)(attn + base + t*4) = v0;
    *(float4*)(attn + base + 1024 + t*4) = v1;
}

// ============================================================
// ctx: per (b,h): C[128 x 64] tile = attn[128 x S] @ V[S x 64]
// ============================================================
__global__ __launch_bounds__(256, 2)
void ctx128(const float* __restrict__ attn)
{
    __shared__ float As[2][16][PADW];
    __shared__ float Vs[2][16][64];
    const int bh = blockIdx.y;
    const int b = bh >> 4, h = bh & 15;
    const int i0 = blockIdx.x * 128;
    const int t = threadIdx.x;
    const int lane = t & 31, warp = t >> 5;
    const int wm = warp >> 1, wn = warp & 1;
    const int tm = lane >> 3, tn = lane & 7;
    const int lrow = t >> 2;
    const int lkc  = (t & 3) * 4;
    const int vrow = t >> 4;          // 0..15
    const int vnc  = (t & 15) * 4;    // 0..60

    const float* Ap = attn + ((size_t)bh*SS + i0 + lrow)*SS + lkc;
    const float* Vp = g_V + (size_t)b*SS*DD + h*DK + (size_t)vrow*DD + vnc;

    ull acc[2][4][2];
#pragma unroll
    for (int a = 0; a < 2; a++)
#pragma unroll
        for (int c = 0; c < 4; c++)
#pragma unroll
            for (int d = 0; d < 2; d++) acc[a][c][d] = 0ull;

    {
        float4 a0 = *(const float4*)(Ap);
        float4 a1 = *(const float4*)(Ap + (size_t)64*SS);
        float4 vv = *(const float4*)(Vp);
        As[0][lkc+0][lrow] = a0.x; As[0][lkc+1][lrow] = a0.y;
        As[0][lkc+2][lrow] = a0.z; As[0][lkc+3][lrow] = a0.w;
        As[0][lkc+0][lrow+64] = a1.x; As[0][lkc+1][lrow+64] = a1.y;
        As[0][lkc+2][lrow+64] = a1.z; As[0][lkc+3][lrow+64] = a1.w;
        *(float4*)&Vs[0][vrow][vnc] = vv;
    }
    __syncthreads();

    int buf = 0;
    for (int k0 = 0; k0 < SS; k0 += 16) {
        float4 na0, na1, nvv;
        const bool more = (k0 + 16 < SS);
        if (more) {
            na0 = *(const float4*)(Ap + k0 + 16);
            na1 = *(const float4*)(Ap + (size_t)64*SS + k0 + 16);
            nvv = *(const float4*)(Vp + (size_t)(k0 + 16)*DD);
        }
#pragma unroll
        for (int kk = 0; kk < 16; kk++) {
            const float4 a0 = *(const float4*)&As[buf][kk][wm*32 + tm*4];
            const float4 a1 = *(const float4*)&As[buf][kk][wm*32 + 16 + tm*4];
            const float4 bv = *(const float4*)&Vs[buf][kk][wn*32 + tn*4];
            ull bp[2] = {pk2(bv.x, bv.y), pk2(bv.z, bv.w)};
            float av[2][4] = {{a0.x,a0.y,a0.z,a0.w},{a1.x,a1.y,a1.z,a1.w}};
#pragma unroll
            for (int ri = 0; ri < 2; ri++)
#pragma unroll
                for (int ii = 0; ii < 4; ii++) {
                    ull ad = dup2(av[ri][ii]);
                    fma2(acc[ri][ii][0], ad, bp[0]);
                    fma2(acc[ri][ii][1], ad, bp[1]);
                }
        }
        if (more) {
            const int nb = buf ^ 1;
            As[nb][lkc+0][lrow] = na0.x; As[nb][lkc+1][lrow] = na0.y;
            As[nb][lkc+2][lrow] = na0.z; As[nb][lkc+3][lrow] = na0.w;
            As[nb][lkc+0][lrow+64] = na1.x; As[nb][lkc+1][lrow+64] = na1.y;
            As[nb][lkc+2][lrow+64] = na1.z; As[nb][lkc+3][lrow+64] = na1.w;
            *(float4*)&Vs[nb][vrow][vnc] = nvv;
        }
        __syncthreads();
        buf ^= 1;
    }

#pragma unroll
    for (int ri = 0; ri < 2; ri++)
#pragma unroll
        for (int ii = 0; ii < 4; ii++) {
            const int i = i0 + wm*32 + ri*16 + tm*4 + ii;
            float2 p0 = up2(acc[ri][ii][0]);
            float2 p1 = up2(acc[ri][ii][1]);
            float4 v = make_float4(p0.x, p0.y, p1.x, p1.y);
            *(float4*)&g_ctx[((size_t)b*SS + i)*DD + h*DK + wn*32 + tn*4] = v;
        }
}

// ============================================================
// out = LayerNorm(pre + residual)
// ============================================================
__global__ void ln_kernel(const float* __restrict__ resid,
                          float* __restrict__ out)
{
    const size_t base = (size_t)blockIdx.x * DD;
    const int t = threadIdx.x;
    __shared__ float red1[8];
    __shared__ float red2[8];

    float v[4];
    float s = 0.f;
#pragma unroll
    for (int j = 0; j < 4; j++) {
        v[j] = g_pre[base + t + 256*j] + resid[base + t + 256*j];
        s += v[j];
    }
#pragma unroll
    for (int o = 16; o > 0; o >>= 1) s += __shfl_xor_sync(0xffffffffu, s, o);
    if ((t & 31) == 0) red1[t >> 5] = s;
    __syncthreads();
    s = red1[0];
#pragma unroll
    for (int w = 1; w < 8; w++) s += red1[w];
    const float mu = s * (1.0f / DD);

    float sq = 0.f;
#pragma unroll
    for (int j = 0; j < 4; j++) { const float d = v[j] - mu; sq += d*d; }
#pragma unroll
    for (int o = 16; o > 0; o >>= 1) sq += __shfl_xor_sync(0xffffffffu, sq, o);
    if ((t & 31) == 0) red2[t >> 5] = sq;
    __syncthreads();
    sq = red2[0];
#pragma unroll
    for (int w = 1; w < 8; w++) sq += red2[w];
    const float inv = rsqrtf(sq * (1.0f / DD) + 1e-5f);

#pragma unroll
    for (int j = 0; j < 4; j++) out[base + t + 256*j] = (v[j] - mu) * inv;
}

// ============================================================
extern "C" void kernel_launch(void* const* d_in, const int* in_sizes, int n_in,
                              void* d_out, int out_size)
{
    const float* inQ  = (const float*)d_in[0];
    const float* inK  = (const float*)d_in[1];
    const float* inV  = (const float*)d_in[2];
    const int*   mask = (const int*)  d_in[3];
    const float* WQ   = (const float*)d_in[4];
    const float* WK   = (const float*)d_in[5];
    const float* WV   = (const float*)d_in[6];
    const float* Wfc  = (const float*)d_in[7];
    float* out = (float*)d_out;

    float *pQ, *pK, *pV, *pctx, *ppre, *psc, *pdmy;
    cudaGetSymbolAddress((void**)&pQ,   g_Q);
    cudaGetSymbolAddress((void**)&pK,   g_K);
    cudaGetSymbolAddress((void**)&pV,   g_V);
    cudaGetSymbolAddress((void**)&pctx, g_ctx);
    cudaGetSymbolAddress((void**)&ppre, g_pre);
    cudaGetSymbolAddress((void**)&psc,  g_scores);
    cudaGetSymbolAddress((void**)&pdmy, g_dummy_out);

    const long long OUT_E  = (long long)NT * DD;
    const long long ATTN_E = (long long)BB * HH * SS * SS;

    float* out_dst  = out;
    float* attn_dst = psc;
    if ((long long)out_size >= OUT_E + ATTN_E) {
        attn_dst = out + OUT_E;
    } else if ((long long)out_size == ATTN_E) {
        attn_dst = out;
        out_dst  = pdmy;
    }

    const dim3 blk(256);

    gemm_nt128<<<dim3(DD/128, NT/128), blk>>>(inQ, WQ, pQ, NT, DD, DD);
    gemm_nt128<<<dim3(DD/128, NT/128), blk>>>(inK, WK, pK, NT, DD, DD);
    gemm_nt128<<<dim3(DD/128, NT/128), blk>>>(inV, WV, pV, NT, DD, DD);

    scores128<<<dim3(SS/128, SS/128, BB*HH), blk>>>(mask);

    softmax_kernel<<<(unsigned)(BB*HH*SS), blk>>>(psc, attn_dst);

    ctx128<<<dim3(SS/128, BB*HH), blk>>>(attn_dst);

    gemm_nt128<<<dim3(DD/128, NT/128), blk>>>(pctx, Wfc, ppre, NT, DD, DD);

    ln_kernel<<<(unsigned)NT, blk>>>(inQ, out_dst);
}

// round 5
// speedup vs baseline: 2.0544x; 1.3432x over previous
#include <cuda_runtime.h>
#include <cuda_bf16.h>
#include <cstdint>
#include <math.h>

#define BB 2
#define SS 2048
#define DD 1024
#define HH 16
#define DK 64
#define NT (BB*SS)   // 4096 tokens
#define PADW 132

typedef unsigned long long ull;

// ---- scratch (static device globals; no allocations) ----
__device__ float g_Q[(size_t)NT*DD];
__device__ float g_K[(size_t)NT*DD];
__device__ float g_V[(size_t)NT*DD];
__device__ float g_ctx[(size_t)NT*DD];
__device__ float g_pre[(size_t)NT*DD];
__device__ float g_scores[(size_t)BB*HH*SS*SS];
__device__ float g_dummy_out[(size_t)NT*DD];

// ---- packed fp32x2 helpers (sm_103a FFMA2) ----
__device__ __forceinline__ ull pk2(float x, float y) {
    ull r;
    asm("mov.b64 %0, {%1, %2};" : "=l"(r)
        : "r"(__float_as_uint(x)), "r"(__float_as_uint(y)));
    return r;
}
__device__ __forceinline__ ull dup2(float x) { return pk2(x, x); }
__device__ __forceinline__ void fma2(ull& d, ull a, ull b) {
    asm("fma.rn.f32x2 %0, %1, %2, %0;" : "+l"(d) : "l"(a), "l"(b));
}
__device__ __forceinline__ float2 up2(ull v) {
    unsigned lo, hi;
    asm("mov.b64 {%0, %1}, %2;" : "=r"(lo), "=r"(hi) : "l"(v));
    return make_float2(__uint_as_float(lo), __uint_as_float(hi));
}

// ============================================================
// warp-MMA helpers (baseline PTX: sm_80+, no 'a' features)
// ============================================================
__device__ __forceinline__ uint32_t smem_u32(const void* p) {
    uint32_t a;
    asm("{ .reg .u64 t; cvta.to.shared.u64 t, %1; cvt.u32.u64 %0, t; }"
        : "=r"(a) : "l"(p));
    return a;
}
__device__ __forceinline__ void ldsm_x4(uint32_t* r, uint32_t addr) {
    asm volatile("ldmatrix.sync.aligned.m8n8.x4.shared.b16 {%0,%1,%2,%3}, [%4];"
        : "=r"(r[0]), "=r"(r[1]), "=r"(r[2]), "=r"(r[3]) : "r"(addr));
}
__device__ __forceinline__ void mma_bf16(float* c, const uint32_t* a, const uint32_t* b) {
    asm volatile(
        "mma.sync.aligned.m16n8k16.row.col.f32.bf16.bf16.f32 "
        "{%0,%1,%2,%3}, {%4,%5,%6,%7}, {%8,%9}, {%0,%1,%2,%3};"
        : "+f"(c[0]), "+f"(c[1]), "+f"(c[2]), "+f"(c[3])
        : "r"(a[0]), "r"(a[1]), "r"(a[2]), "r"(a[3]), "r"(b[0]), "r"(b[1]));
}

// fp32x8 -> bf16 hi/lo split
__device__ __forceinline__ void split8(const float4& x, const float4& y,
                                       uint4& hi, uint4& lo) {
    float f[8] = {x.x, x.y, x.z, x.w, y.x, y.y, y.z, y.w};
    uint32_t h[4], l[4];
#pragma unroll
    for (int j = 0; j < 4; j++) {
        float a = f[2*j], b = f[2*j+1];
        __nv_bfloat162 hb = __float22bfloat162_rn(make_float2(a, b));
        float2 hf = __bfloat1622float2(hb);
        __nv_bfloat162 lb = __float22bfloat162_rn(make_float2(a - hf.x, b - hf.y));
        h[j] = *(uint32_t*)&hb;
        l[j] = *(uint32_t*)&lb;
    }
    hi = make_uint4(h[0], h[1], h[2], h[3]);
    lo = make_uint4(l[0], l[1], l[2], l[3]);
}

// smem tile layout (per buffer): Ah,Al,Bh,Bl each 128 rows x 48 bytes
#define T_AH 0
#define T_AL 6144
#define T_BH 12288
#define T_BL 18432
#define BUFB 24576
#define DYNSM (2*BUFB)   // 49152 = 48KB

__device__ __forceinline__ void stage_chunk(char* sm, int bufbase, int stoff,
                                            const float4& a0, const float4& a1,
                                            const float4& b0, const float4& b1)
{
    uint4 hi, lo;
    split8(a0, a1, hi, lo);
    *(uint4*)(sm + bufbase + T_AH + stoff) = hi;
    *(uint4*)(sm + bufbase + T_AL + stoff) = lo;
    split8(b0, b1, hi, lo);
    *(uint4*)(sm + bufbase + T_BH + stoff) = hi;
    *(uint4*)(sm + bufbase + T_BL + stoff) = lo;
}

__device__ __forceinline__ void mma_pass(float acc[2][8][4],
                                         uint32_t Af[2][4], uint32_t Bf[4][4])
{
#pragma unroll
    for (int ti = 0; ti < 2; ti++)
#pragma unroll
        for (int tj = 0; tj < 8; tj++)
            mma_bf16(acc[ti][tj], Af[ti], &Bf[tj >> 1][(tj & 1) * 2]);
}

// core: acc += A[128 x 16*nchunks] @ B[128 x 16*nchunks]^T (bf16 hi/lo, 3 products)
// ApT/BpT: this thread's staging pointers (row i0+(t>>1), col (t&1)*8), row
// strides already applied; chunk s advances by +16 floats.
__device__ __forceinline__ void mma_core(const float* ApT, const float* BpT,
                                         int nchunks, char* sm, uint32_t smb,
                                         int t, float acc[2][8][4])
{
    const int lane = t & 31, warp = t >> 5;
    const int wm = warp >> 1, wn = warp & 1;
    const int stoff = (t >> 1) * 48 + (t & 1) * 16;

    const uint32_t a_off = (uint32_t)((wm*32 + (lane & 15)) * 48 + ((lane >> 4) & 1) * 16);
    const uint32_t b_off = (uint32_t)((wn*64 + (lane & 7) + ((lane >> 4) & 1) * 8) * 48
                                      + ((lane >> 3) & 1) * 16);

    float4 a0 = *(const float4*)(ApT);
    float4 a1 = *(const float4*)(ApT + 4);
    float4 b0 = *(const float4*)(BpT);
    float4 b1 = *(const float4*)(BpT + 4);
    stage_chunk(sm, 0, stoff, a0, a1, b0, b1);
    __syncthreads();

    for (int s = 0; s < nchunks; s++) {
        const int buf = (s & 1) * BUFB;
        const bool more = (s + 1 < nchunks);
        if (more) {
            a0 = *(const float4*)(ApT + (s+1)*16);
            a1 = *(const float4*)(ApT + (s+1)*16 + 4);
            b0 = *(const float4*)(BpT + (s+1)*16);
            b1 = *(const float4*)(BpT + (s+1)*16 + 4);
        }
        uint32_t Ah[2][4], Bh[4][4], X[4][4];
#pragma unroll
        for (int ti = 0; ti < 2; ti++)
            ldsm_x4(Ah[ti], smb + buf + T_AH + a_off + ti*16*48);
#pragma unroll
        for (int pj = 0; pj < 4; pj++)
            ldsm_x4(Bh[pj], smb + buf + T_BH + b_off + pj*16*48);
        mma_pass(acc, Ah, Bh);
#pragma unroll
        for (int pj = 0; pj < 4; pj++)
            ldsm_x4(X[pj], smb + buf + T_BL + b_off + pj*16*48);
        mma_pass(acc, Ah, X);
#pragma unroll
        for (int ti = 0; ti < 2; ti++)
            ldsm_x4(X[ti], smb + buf + T_AL + a_off + ti*16*48);
        mma_pass(acc, X, Bh);

        if (more) {
            __syncthreads();   // all warps done computing chunk s
            stage_chunk(sm, buf ^ BUFB, stoff, a0, a1, b0, b1);
            __syncthreads();   // stores visible
        }
    }
}

// ============================================================
// projections: C[M,N] = A[M,K] @ B[N,K]^T (fp32 io, bf16-split MMA)
// ============================================================
__global__ __launch_bounds__(256, 2)
void gemm_mma(const float* __restrict__ A, const float* __restrict__ B,
              float* __restrict__ C, int N, int K)
{
    extern __shared__ __align__(128) char sm[];
    const uint32_t smb = smem_u32(sm);
    const int t = threadIdx.x;
    const int i0 = blockIdx.y * 128, j0 = blockIdx.x * 128;

    float acc[2][8][4];
#pragma unroll
    for (int a = 0; a < 2; a++)
#pragma unroll
        for (int b = 0; b < 8; b++)
#pragma unroll
            for (int c = 0; c < 4; c++) acc[a][b][c] = 0.f;

    const int r = t >> 1, kc = (t & 1) * 8;
    const float* ApT = A + (size_t)(i0 + r) * K + kc;
    const float* BpT = B + (size_t)(j0 + r) * K + kc;

    mma_core(ApT, BpT, K / 16, sm, smb, t, acc);

    const int lane = t & 31, warp = t >> 5;
    const int wm = warp >> 1, wn = warp & 1;
    const int rb = i0 + wm*32 + (lane >> 2);
    const int cb = j0 + wn*64 + (lane & 3) * 2;
#pragma unroll
    for (int ti = 0; ti < 2; ti++)
#pragma unroll
        for (int tj = 0; tj < 8; tj++) {
            const int i = rb + ti*16, j = cb + tj*8;
            *(float2*)&C[(size_t)i*N + j]     = make_float2(acc[ti][tj][0], acc[ti][tj][1]);
            *(float2*)&C[(size_t)(i+8)*N + j] = make_float2(acc[ti][tj][2], acc[ti][tj][3]);
        }
}

// ============================================================
// scores: (Q.K^T)/8 + mask per head via bf16-split MMA, K=64.
// ============================================================
__global__ __launch_bounds__(256, 2)
void scores_mma(const int* __restrict__ mask)
{
    extern __shared__ __align__(128) char sm[];
    const uint32_t smb = smem_u32(sm);
    const int t = threadIdx.x;
    const int bh = blockIdx.z;
    const int b = bh >> 4, h = bh & 15;
    const int i0 = blockIdx.y * 128, j0 = blockIdx.x * 128;

    float acc[2][8][4];
#pragma unroll
    for (int a = 0; a < 2; a++)
#pragma unroll
        for (int c = 0; c < 8; c++)
#pragma unroll
            for (int d = 0; d < 4; d++) acc[a][c][d] = 0.f;

    const int r = t >> 1, kc = (t & 1) * 8;
    const float* ApT = g_Q + (size_t)b*SS*DD + (size_t)(i0 + r)*DD + h*DK + kc;
    const float* BpT = g_K + (size_t)b*SS*DD + (size_t)(j0 + r)*DD + h*DK + kc;

    mma_core(ApT, BpT, DK / 16, sm, smb, t, acc);

    const int lane = t & 31, warp = t >> 5;
    const int wm = warp >> 1, wn = warp & 1;
    const int rb = i0 + wm*32 + (lane >> 2);
    const int cb = j0 + wn*64 + (lane & 3) * 2;
    const int* mb = mask + (size_t)b*SS*SS;
    float* srow = g_scores + (size_t)bh*SS*SS;
#pragma unroll
    for (int ti = 0; ti < 2; ti++)
#pragma unroll
        for (int tj = 0; tj < 8; tj++) {
            const int i = rb + ti*16, j = cb + tj*8;
            int2 m0 = *(const int2*)&mb[(size_t)i*SS + j];
            int2 m1 = *(const int2*)&mb[(size_t)(i+8)*SS + j];
            float2 v0 = make_float2(m0.x ? -1e9f : acc[ti][tj][0]*0.125f,
                                    m0.y ? -1e9f : acc[ti][tj][1]*0.125f);
            float2 v1 = make_float2(m1.x ? -1e9f : acc[ti][tj][2]*0.125f,
                                    m1.y ? -1e9f : acc[ti][tj][3]*0.125f);
            *(float2*)&srow[(size_t)i*SS + j]     = v0;
            *(float2*)&srow[(size_t)(i+8)*SS + j] = v1;
        }
}

// ============================================================
// softmax over rows of length SS=2048, vectorized.
// ============================================================
__global__ void softmax_kernel(const float* __restrict__ sc,
                               float* __restrict__ attn)
{
    const size_t base = (size_t)blockIdx.x * SS;
    const int t = threadIdx.x;
    __shared__ float redm[8];
    __shared__ float reds[8];

    float4 v0 = *(const float4*)(sc + base + t*4);
    float4 v1 = *(const float4*)(sc + base + 1024 + t*4);

    float m = fmaxf(fmaxf(fmaxf(v0.x, v0.y), fmaxf(v0.z, v0.w)),
                    fmaxf(fmaxf(v1.x, v1.y), fmaxf(v1.z, v1.w)));
#pragma unroll
    for (int o = 16; o > 0; o >>= 1) m = fmaxf(m, __shfl_xor_sync(0xffffffffu, m, o));
    if ((t & 31) == 0) redm[t >> 5] = m;
    __syncthreads();
    m = redm[0];
#pragma unroll
    for (int w = 1; w < 8; w++) m = fmaxf(m, redm[w]);

    v0.x = __expf(v0.x - m); v0.y = __expf(v0.y - m);
    v0.z = __expf(v0.z - m); v0.w = __expf(v0.w - m);
    v1.x = __expf(v1.x - m); v1.y = __expf(v1.y - m);
    v1.z = __expf(v1.z - m); v1.w = __expf(v1.w - m);
    float s = (v0.x + v0.y) + (v0.z + v0.w) + (v1.x + v1.y) + (v1.z + v1.w);
#pragma unroll
    for (int o = 16; o > 0; o >>= 1) s += __shfl_xor_sync(0xffffffffu, s, o);
    if ((t & 31) == 0) reds[t >> 5] = s;
    __syncthreads();
    s = reds[0];
#pragma unroll
    for (int w = 1; w < 8; w++) s += reds[w];

    const float inv = 1.0f / s;
    v0.x *= inv; v0.y *= inv; v0.z *= inv; v0.w *= inv;
    v1.x *= inv; v1.y *= inv; v1.z *= inv; v1.w *= inv;
    *(float4*)(attn + base + t*4) = v0;
    *(float4*)(attn + base + 1024 + t*4) = v1;
}

// ============================================================
// ctx: per (b,h): C[128 x 64] tile = attn[128 x S] @ V[S x 64] (FFMA2)
// ============================================================
__global__ __launch_bounds__(256, 2)
void ctx128(const float* __restrict__ attn)
{
    __shared__ float As[2][16][PADW];
    __shared__ float Vs[2][16][64];
    const int bh = blockIdx.y;
    const int b = bh >> 4, h = bh & 15;
    const int i0 = blockIdx.x * 128;
    const int t = threadIdx.x;
    const int lane = t & 31, warp = t >> 5;
    const int wm = warp >> 1, wn = warp & 1;
    const int tm = lane >> 3, tn = lane & 7;
    const int lrow = t >> 2;
    const int lkc  = (t & 3) * 4;
    const int vrow = t >> 4;          // 0..15
    const int vnc  = (t & 15) * 4;    // 0..60

    const float* Ap = attn + ((size_t)bh*SS + i0 + lrow)*SS + lkc;
    const float* Vp = g_V + (size_t)b*SS*DD + h*DK + (size_t)vrow*DD + vnc;

    ull acc[2][4][2];
#pragma unroll
    for (int a = 0; a < 2; a++)
#pragma unroll
        for (int c = 0; c < 4; c++)
#pragma unroll
            for (int d = 0; d < 2; d++) acc[a][c][d] = 0ull;

    {
        float4 a0 = *(const float4*)(Ap);
        float4 a1 = *(const float4*)(Ap + (size_t)64*SS);
        float4 vv = *(const float4*)(Vp);
        As[0][lkc+0][lrow] = a0.x; As[0][lkc+1][lrow] = a0.y;
        As[0][lkc+2][lrow] = a0.z; As[0][lkc+3][lrow] = a0.w;
        As[0][lkc+0][lrow+64] = a1.x; As[0][lkc+1][lrow+64] = a1.y;
        As[0][lkc+2][lrow+64] = a1.z; As[0][lkc+3][lrow+64] = a1.w;
        *(float4*)&Vs[0][vrow][vnc] = vv;
    }
    __syncthreads();

    int buf = 0;
    for (int k0 = 0; k0 < SS; k0 += 16) {
        float4 na0, na1, nvv;
        const bool more = (k0 + 16 < SS);
        if (more) {
            na0 = *(const float4*)(Ap + k0 + 16);
            na1 = *(const float4*)(Ap + (size_t)64*SS + k0 + 16);
            nvv = *(const float4*)(Vp + (size_t)(k0 + 16)*DD);
        }
#pragma unroll
        for (int kk = 0; kk < 16; kk++) {
            const float4 a0 = *(const float4*)&As[buf][kk][wm*32 + tm*4];
            const float4 a1 = *(const float4*)&As[buf][kk][wm*32 + 16 + tm*4];
            const float4 bv = *(const float4*)&Vs[buf][kk][wn*32 + tn*4];
            ull bp[2] = {pk2(bv.x, bv.y), pk2(bv.z, bv.w)};
            float av[2][4] = {{a0.x,a0.y,a0.z,a0.w},{a1.x,a1.y,a1.z,a1.w}};
#pragma unroll
            for (int ri = 0; ri < 2; ri++)
#pragma unroll
                for (int ii = 0; ii < 4; ii++) {
                    ull ad = dup2(av[ri][ii]);
                    fma2(acc[ri][ii][0], ad, bp[0]);
                    fma2(acc[ri][ii][1], ad, bp[1]);
                }
        }
        if (more) {
            const int nb = buf ^ 1;
            As[nb][lkc+0][lrow] = na0.x; As[nb][lkc+1][lrow] = na0.y;
            As[nb][lkc+2][lrow] = na0.z; As[nb][lkc+3][lrow] = na0.w;
            As[nb][lkc+0][lrow+64] = na1.x; As[nb][lkc+1][lrow+64] = na1.y;
            As[nb][lkc+2][lrow+64] = na1.z; As[nb][lkc+3][lrow+64] = na1.w;
            *(float4*)&Vs[nb][vrow][vnc] = nvv;
        }
        __syncthreads();
        buf ^= 1;
    }

#pragma unroll
    for (int ri = 0; ri < 2; ri++)
#pragma unroll
        for (int ii = 0; ii < 4; ii++) {
            const int i = i0 + wm*32 + ri*16 + tm*4 + ii;
            float2 p0 = up2(acc[ri][ii][0]);
            float2 p1 = up2(acc[ri][ii][1]);
            float4 v = make_float4(p0.x, p0.y, p1.x, p1.y);
            *(float4*)&g_ctx[((size_t)b*SS + i)*DD + h*DK + wn*32 + tn*4] = v;
        }
}

// ============================================================
// out = LayerNorm(pre + residual)
// ============================================================
__global__ void ln_kernel(const float* __restrict__ resid,
                          float* __restrict__ out)
{
    const size_t base = (size_t)blockIdx.x * DD;
    const int t = threadIdx.x;
    __shared__ float red1[8];
    __shared__ float red2[8];

    float v[4];
    float s = 0.f;
#pragma unroll
    for (int j = 0; j < 4; j++) {
        v[j] = g_pre[base + t + 256*j] + resid[base + t + 256*j];
        s += v[j];
    }
#pragma unroll
    for (int o = 16; o > 0; o >>= 1) s += __shfl_xor_sync(0xffffffffu, s, o);
    if ((t & 31) == 0) red1[t >> 5] = s;
    __syncthreads();
    s = red1[0];
#pragma unroll
    for (int w = 1; w < 8; w++) s += red1[w];
    const float mu = s * (1.0f / DD);

    float sq = 0.f;
#pragma unroll
    for (int j = 0; j < 4; j++) { const float d = v[j] - mu; sq += d*d; }
#pragma unroll
    for (int o = 16; o > 0; o >>= 1) sq += __shfl_xor_sync(0xffffffffu, sq, o);
    if ((t & 31) == 0) red2[t >> 5] = sq;
    __syncthreads();
    sq = red2[0];
#pragma unroll
    for (int w = 1; w < 8; w++) sq += red2[w];
    const float inv = rsqrtf(sq * (1.0f / DD) + 1e-5f);

#pragma unroll
    for (int j = 0; j < 4; j++) out[base + t + 256*j] = (v[j] - mu) * inv;
}

// ============================================================
extern "C" void kernel_launch(void* const* d_in, const int* in_sizes, int n_in,
                              void* d_out, int out_size)
{
    const float* inQ  = (const float*)d_in[0];
    const float* inK  = (const float*)d_in[1];
    const float* inV  = (const float*)d_in[2];
    const int*   mask = (const int*)  d_in[3];
    const float* WQ   = (const float*)d_in[4];
    const float* WK   = (const float*)d_in[5];
    const float* WV   = (const float*)d_in[6];
    const float* Wfc  = (const float*)d_in[7];
    float* out = (float*)d_out;

    float *pQ, *pK, *pV, *pctx, *ppre, *psc, *pdmy;
    cudaGetSymbolAddress((void**)&pQ,   g_Q);
    cudaGetSymbolAddress((void**)&pK,   g_K);
    cudaGetSymbolAddress((void**)&pV,   g_V);
    cudaGetSymbolAddress((void**)&pctx, g_ctx);
    cudaGetSymbolAddress((void**)&ppre, g_pre);
    cudaGetSymbolAddress((void**)&psc,  g_scores);
    cudaGetSymbolAddress((void**)&pdmy, g_dummy_out);

    const long long OUT_E  = (long long)NT * DD;
    const long long ATTN_E = (long long)BB * HH * SS * SS;

    float* out_dst  = out;
    float* attn_dst = psc;
    if ((long long)out_size >= OUT_E + ATTN_E) {
        attn_dst = out + OUT_E;
    } else if ((long long)out_size == ATTN_E) {
        attn_dst = out;
        out_dst  = pdmy;
    }

    const dim3 blk(256);

    // projections on warp-MMA (bf16 hi/lo split, fp32-class accuracy)
    gemm_mma<<<dim3(DD/128, NT/128), blk, DYNSM>>>(inQ, WQ, pQ, DD, DD);
    gemm_mma<<<dim3(DD/128, NT/128), blk, DYNSM>>>(inK, WK, pK, DD, DD);
    gemm_mma<<<dim3(DD/128, NT/128), blk, DYNSM>>>(inV, WV, pV, DD, DD);

    // scores + mask on warp-MMA
    scores_mma<<<dim3(SS/128, SS/128, BB*HH), blk, DYNSM>>>(mask);

    softmax_kernel<<<(unsigned)(BB*HH*SS), blk>>>(psc, attn_dst);

    ctx128<<<dim3(SS/128, BB*HH), blk>>>(attn_dst);

    gemm_mma<<<dim3(DD/128, NT/128), blk, DYNSM>>>(pctx, Wfc, ppre, DD, DD);

    ln_kernel<<<(unsigned)NT, blk>>>(inQ, out_dst);
}

// round 6
// speedup vs baseline: 2.0983x; 1.0214x over previous
#include <cuda_runtime.h>
#include <cuda_bf16.h>
#include <cstdint>
#include <math.h>

#define BB 2
#define SS 2048
#define DD 1024
#define HH 16
#define DK 64
#define NT (BB*SS)   // 4096 tokens

// ---- scratch (static device globals; no allocations) ----
__device__ float g_Q[(size_t)NT*DD];
__device__ float g_K[(size_t)NT*DD];
__device__ float g_V[(size_t)NT*DD];
__device__ float g_ctx[(size_t)NT*DD];
__device__ float g_pre[(size_t)NT*DD];
__device__ float g_scores[(size_t)BB*HH*SS*SS];   // fallback attn target only
__device__ float g_dummy_out[(size_t)NT*DD];
__device__ float g_mh[(size_t)32*16*16*128];      // per-tile running max history
__device__ float g_mf[(size_t)32*SS];             // final row max
__device__ float g_ls[(size_t)32*SS];             // final row sum

// ============================================================
// warp-MMA helpers (baseline PTX: sm_80+, no 'a' features)
// ============================================================
__device__ __forceinline__ uint32_t smem_u32(const void* p) {
    uint32_t a;
    asm("{ .reg .u64 t; cvta.to.shared.u64 t, %1; cvt.u32.u64 %0, t; }"
        : "=r"(a) : "l"(p));
    return a;
}
__device__ __forceinline__ void ldsm_x4(uint32_t* r, uint32_t addr) {
    asm volatile("ldmatrix.sync.aligned.m8n8.x4.shared.b16 {%0,%1,%2,%3}, [%4];"
        : "=r"(r[0]), "=r"(r[1]), "=r"(r[2]), "=r"(r[3]) : "r"(addr));
}
__device__ __forceinline__ void ldsm_x4_t(uint32_t* r, uint32_t addr) {
    asm volatile("ldmatrix.sync.aligned.m8n8.x4.trans.shared.b16 {%0,%1,%2,%3}, [%4];"
        : "=r"(r[0]), "=r"(r[1]), "=r"(r[2]), "=r"(r[3]) : "r"(addr));
}
__device__ __forceinline__ void mma_bf16(float* c, const uint32_t* a, const uint32_t* b) {
    asm volatile(
        "mma.sync.aligned.m16n8k16.row.col.f32.bf16.bf16.f32 "
        "{%0,%1,%2,%3}, {%4,%5,%6,%7}, {%8,%9}, {%0,%1,%2,%3};"
        : "+f"(c[0]), "+f"(c[1]), "+f"(c[2]), "+f"(c[3])
        : "r"(a[0]), "r"(a[1]), "r"(a[2]), "r"(a[3]), "r"(b[0]), "r"(b[1]));
}

// fp32x8 -> bf16 hi/lo split
__device__ __forceinline__ void split8(const float4& x, const float4& y,
                                       uint4& hi, uint4& lo) {
    float f[8] = {x.x, x.y, x.z, x.w, y.x, y.y, y.z, y.w};
    uint32_t h[4], l[4];
#pragma unroll
    for (int j = 0; j < 4; j++) {
        float a = f[2*j], b = f[2*j+1];
        __nv_bfloat162 hb = __float22bfloat162_rn(make_float2(a, b));
        float2 hf = __bfloat1622float2(hb);
        __nv_bfloat162 lb = __float22bfloat162_rn(make_float2(a - hf.x, b - hf.y));
        h[j] = *(uint32_t*)&hb;
        l[j] = *(uint32_t*)&lb;
    }
    hi = make_uint4(h[0], h[1], h[2], h[3]);
    lo = make_uint4(l[0], l[1], l[2], l[3]);
}
__device__ __forceinline__ uint32_t packhl(float a, float b, uint32_t& lo) {
    __nv_bfloat162 hb = __float22bfloat162_rn(make_float2(a, b));
    float2 hf = __bfloat1622float2(hb);
    __nv_bfloat162 lb = __float22bfloat162_rn(make_float2(a - hf.x, b - hf.y));
    lo = *(uint32_t*)&lb;
    return *(uint32_t*)&hb;
}

// smem tile layout for gemm_mma (per buffer): Ah,Al,Bh,Bl each 128 rows x 48 bytes
#define T_AH 0
#define T_AL 6144
#define T_BH 12288
#define T_BL 18432
#define BUFB 24576
#define DYNSM (2*BUFB)   // 49152 = 48KB

__device__ __forceinline__ void stage_chunk(char* sm, int bufbase, int stoff,
                                            const float4& a0, const float4& a1,
                                            const float4& b0, const float4& b1)
{
    uint4 hi, lo;
    split8(a0, a1, hi, lo);
    *(uint4*)(sm + bufbase + T_AH + stoff) = hi;
    *(uint4*)(sm + bufbase + T_AL + stoff) = lo;
    split8(b0, b1, hi, lo);
    *(uint4*)(sm + bufbase + T_BH + stoff) = hi;
    *(uint4*)(sm + bufbase + T_BL + stoff) = lo;
}

__device__ __forceinline__ void mma_pass(float acc[2][8][4],
                                         uint32_t Af[2][4], uint32_t Bf[4][4])
{
#pragma unroll
    for (int ti = 0; ti < 2; ti++)
#pragma unroll
        for (int tj = 0; tj < 8; tj++)
            mma_bf16(acc[ti][tj], Af[ti], &Bf[tj >> 1][(tj & 1) * 2]);
}

__device__ __forceinline__ void mma_core(const float* ApT, const float* BpT,
                                         int nchunks, char* sm, uint32_t smb,
                                         int t, float acc[2][8][4])
{
    const int lane = t & 31, warp = t >> 5;
    const int wm = warp >> 1, wn = warp & 1;
    const int stoff = (t >> 1) * 48 + (t & 1) * 16;

    const uint32_t a_off = (uint32_t)((wm*32 + (lane & 15)) * 48 + ((lane >> 4) & 1) * 16);
    const uint32_t b_off = (uint32_t)((wn*64 + (lane & 7) + ((lane >> 4) & 1) * 8) * 48
                                      + ((lane >> 3) & 1) * 16);

    float4 a0 = *(const float4*)(ApT);
    float4 a1 = *(const float4*)(ApT + 4);
    float4 b0 = *(const float4*)(BpT);
    float4 b1 = *(const float4*)(BpT + 4);
    stage_chunk(sm, 0, stoff, a0, a1, b0, b1);
    __syncthreads();

    for (int s = 0; s < nchunks; s++) {
        const int buf = (s & 1) * BUFB;
        const bool more = (s + 1 < nchunks);
        if (more) {
            a0 = *(const float4*)(ApT + (s+1)*16);
            a1 = *(const float4*)(ApT + (s+1)*16 + 4);
            b0 = *(const float4*)(BpT + (s+1)*16);
            b1 = *(const float4*)(BpT + (s+1)*16 + 4);
        }
        uint32_t Ah[2][4], Bh[4][4], X[4][4];
#pragma unroll
        for (int ti = 0; ti < 2; ti++)
            ldsm_x4(Ah[ti], smb + buf + T_AH + a_off + ti*16*48);
#pragma unroll
        for (int pj = 0; pj < 4; pj++)
            ldsm_x4(Bh[pj], smb + buf + T_BH + b_off + pj*16*48);
        mma_pass(acc, Ah, Bh);
#pragma unroll
        for (int pj = 0; pj < 4; pj++)
            ldsm_x4(X[pj], smb + buf + T_BL + b_off + pj*16*48);
        mma_pass(acc, Ah, X);
#pragma unroll
        for (int ti = 0; ti < 2; ti++)
            ldsm_x4(X[ti], smb + buf + T_AL + a_off + ti*16*48);
        mma_pass(acc, X, Bh);

        if (more) {
            __syncthreads();
            stage_chunk(sm, buf ^ BUFB, stoff, a0, a1, b0, b1);
            __syncthreads();
        }
    }
}

// ============================================================
// projections: C[M,N] = A[M,K] @ B[N,K]^T (fp32 io, bf16-split MMA)
// ============================================================
__global__ __launch_bounds__(256, 2)
void gemm_mma(const float* __restrict__ A, const float* __restrict__ B,
              float* __restrict__ C, int N, int K)
{
    extern __shared__ __align__(128) char sm[];
    const uint32_t smb = smem_u32(sm);
    const int t = threadIdx.x;
    const int i0 = blockIdx.y * 128, j0 = blockIdx.x * 128;

    float acc[2][8][4];
#pragma unroll
    for (int a = 0; a < 2; a++)
#pragma unroll
        for (int b = 0; b < 8; b++)
#pragma unroll
            for (int c = 0; c < 4; c++) acc[a][b][c] = 0.f;

    const int r = t >> 1, kc = (t & 1) * 8;
    const float* ApT = A + (size_t)(i0 + r) * K + kc;
    const float* BpT = B + (size_t)(j0 + r) * K + kc;

    mma_core(ApT, BpT, K / 16, sm, smb, t, acc);

    const int lane = t & 31, warp = t >> 5;
    const int wm = warp >> 1, wn = warp & 1;
    const int rb = i0 + wm*32 + (lane >> 2);
    const int cb = j0 + wn*64 + (lane & 3) * 2;
#pragma unroll
    for (int ti = 0; ti < 2; ti++)
#pragma unroll
        for (int tj = 0; tj < 8; tj++) {
            const int i = rb + ti*16, j = cb + tj*8;
            *(float2*)&C[(size_t)i*N + j]     = make_float2(acc[ti][tj][0], acc[ti][tj][1]);
            *(float2*)&C[(size_t)(i+8)*N + j] = make_float2(acc[ti][tj][2], acc[ti][tj][3]);
        }
}

// ============================================================
// fused flash attention: per (row-block 128, bh):
//   S = QK^T/8 + mask ; online (m,l) ; write exp(S-m_run) unnorm
//   O = softmax(S) @ V accumulated online ; ctx written normalized
// ============================================================
#define FQ_H 0
#define FQ_L 24576
#define FK_H 49152
#define FK_L 73728
#define FV_H 98304
#define FV_L 116736
#define FSM_M 135168
#define FSM_L 135680
#define FSM_PM 136192
#define FSM_PS 137216
#define DYNSM_F 138240
#define FO_RED 0
#define VROWB 144

__global__ __launch_bounds__(256)
void flash_attn(const int* __restrict__ mask, float* __restrict__ attn)
{
    extern __shared__ __align__(128) char sm[];
    const uint32_t smb = smem_u32(sm);
    const int t = threadIdx.x;
    const int lane = t & 31, warp = t >> 5;
    const int wm = warp >> 1, wn = warp & 1;
    const int rbk = blockIdx.x, bh = blockIdx.y;
    const int b = bh >> 4, h = bh & 15;
    const int i0 = rbk * 128;

    float* msm = (float*)(sm + FSM_M);
    float* lsm = (float*)(sm + FSM_L);
    float* pm  = (float*)(sm + FSM_PM);
    float* ps  = (float*)(sm + FSM_PS);
    if (t < 128) { msm[t] = -INFINITY; lsm[t] = 0.f; }

    const int r = t >> 1, kc = (t & 1) * 8;
    const int stoff = r * 48 + (t & 1) * 16;
    const int vk = t & 127, vn0 = (t >> 7) * 32;

    // stage Q once (4 k-chunks, bf16 hi/lo)
    {
        const float* Qp = g_Q + ((size_t)b*SS + i0 + r)*DD + h*DK + kc;
#pragma unroll
        for (int c = 0; c < 4; c++) {
            float4 q0 = *(const float4*)(Qp + c*16);
            float4 q1 = *(const float4*)(Qp + c*16 + 4);
            uint4 hi, lo;
            split8(q0, q1, hi, lo);
            *(uint4*)(sm + FQ_H + c*6144 + stoff) = hi;
            *(uint4*)(sm + FQ_L + c*6144 + stoff) = lo;
        }
    }

    const uint32_t a_off = (uint32_t)((wm*32 + (lane & 15)) * 48 + ((lane >> 4) & 1) * 16);
    const uint32_t b_off = (uint32_t)((wn*64 + (lane & 7) + ((lane >> 4) & 1) * 8) * 48
                                      + ((lane >> 3) & 1) * 16);

    float acc_o[2][8][4];
#pragma unroll
    for (int a = 0; a < 2; a++)
#pragma unroll
        for (int c = 0; c < 8; c++)
#pragma unroll
            for (int d = 0; d < 4; d++) acc_o[a][c][d] = 0.f;

    const int* mb = mask + (size_t)b*SS*SS;
    float* arow = attn + (size_t)bh*SS*SS;

    for (int jt = 0; jt < 16; jt++) {
        // ---- stage K tile (chunked hi/lo) ----
        {
            const float* Kp = g_K + ((size_t)b*SS + jt*128 + r)*DD + h*DK + kc;
#pragma unroll
            for (int c = 0; c < 4; c++) {
                float4 k0 = *(const float4*)(Kp + c*16);
                float4 k1 = *(const float4*)(Kp + c*16 + 4);
                uint4 hi, lo;
                split8(k0, k1, hi, lo);
                *(uint4*)(sm + FK_H + c*6144 + stoff) = hi;
                *(uint4*)(sm + FK_L + c*6144 + stoff) = lo;
            }
        }
        // ---- stage V tile (rows = k, VROWB-stride, hi/lo) ----
        {
            const float* Vp = g_V + ((size_t)b*SS + jt*128 + vk)*DD + h*DK + vn0;
#pragma unroll
            for (int it = 0; it < 8; it++) {
                float4 v = *(const float4*)(Vp + it*4);
                __nv_bfloat162 h01 = __float22bfloat162_rn(make_float2(v.x, v.y));
                __nv_bfloat162 h23 = __float22bfloat162_rn(make_float2(v.z, v.w));
                float2 f01 = __bfloat1622float2(h01);
                float2 f23 = __bfloat1622float2(h23);
                __nv_bfloat162 l01 = __float22bfloat162_rn(make_float2(v.x - f01.x, v.y - f01.y));
                __nv_bfloat162 l23 = __float22bfloat162_rn(make_float2(v.z - f23.x, v.w - f23.y));
                *(uint2*)(sm + FV_H + vk*VROWB + (vn0 + it*4)*2) =
                    make_uint2(*(uint32_t*)&h01, *(uint32_t*)&h23);
                *(uint2*)(sm + FV_L + vk*VROWB + (vn0 + it*4)*2) =
                    make_uint2(*(uint32_t*)&l01, *(uint32_t*)&l23);
            }
        }
        __syncthreads();

        // ---- S = Q K^T (3-product split) ----
        float acc[2][8][4];
#pragma unroll
        for (int a = 0; a < 2; a++)
#pragma unroll
            for (int c = 0; c < 8; c++)
#pragma unroll
                for (int d = 0; d < 4; d++) acc[a][c][d] = 0.f;
#pragma unroll
        for (int c = 0; c < 4; c++) {
            uint32_t Ah[2][4], Bh[4][4], X[4][4];
#pragma unroll
            for (int ti = 0; ti < 2; ti++)
                ldsm_x4(Ah[ti], smb + FQ_H + c*6144 + a_off + ti*768);
#pragma unroll
            for (int pj = 0; pj < 4; pj++)
                ldsm_x4(Bh[pj], smb + FK_H + c*6144 + b_off + pj*768);
            mma_pass(acc, Ah, Bh);
#pragma unroll
            for (int pj = 0; pj < 4; pj++)
                ldsm_x4(X[pj], smb + FK_L + c*6144 + b_off + pj*768);
            mma_pass(acc, Ah, X);
            uint32_t Al[2][4];
#pragma unroll
            for (int ti = 0; ti < 2; ti++)
                ldsm_x4(Al[ti], smb + FQ_L + c*6144 + a_off + ti*768);
            mma_pass(acc, Al, Bh);
        }

        // ---- mask + scale ----
#pragma unroll
        for (int ti = 0; ti < 2; ti++)
#pragma unroll
            for (int tj = 0; tj < 8; tj++) {
                const int i = i0 + wm*32 + ti*16 + (lane >> 2);
                const int j = jt*128 + wn*64 + tj*8 + (lane & 3)*2;
                int2 m0 = *(const int2*)&mb[(size_t)i*SS + j];
                int2 m1 = *(const int2*)&mb[(size_t)(i+8)*SS + j];
                acc[ti][tj][0] = m0.x ? -1e9f : acc[ti][tj][0]*0.125f;
                acc[ti][tj][1] = m0.y ? -1e9f : acc[ti][tj][1]*0.125f;
                acc[ti][tj][2] = m1.x ? -1e9f : acc[ti][tj][2]*0.125f;
                acc[ti][tj][3] = m1.y ? -1e9f : acc[ti][tj][3]*0.125f;
            }

        // ---- row stats: tile max ----
#pragma unroll
        for (int ti = 0; ti < 2; ti++)
#pragma unroll
            for (int hf = 0; hf < 2; hf++) {
                float mx = -INFINITY;
#pragma unroll
                for (int tj = 0; tj < 8; tj++)
                    mx = fmaxf(mx, fmaxf(acc[ti][tj][hf*2], acc[ti][tj][hf*2+1]));
                mx = fmaxf(mx, __shfl_xor_sync(0xffffffffu, mx, 1));
                mx = fmaxf(mx, __shfl_xor_sync(0xffffffffu, mx, 2));
                if ((lane & 3) == 0)
                    pm[wn*128 + wm*32 + ti*16 + hf*8 + (lane >> 2)] = mx;
            }
        __syncthreads();

        float mnew[2][2], alpha[2][2];
#pragma unroll
        for (int ti = 0; ti < 2; ti++)
#pragma unroll
            for (int hf = 0; hf < 2; hf++) {
                const int row = wm*32 + ti*16 + hf*8 + (lane >> 2);
                const float tmax = fmaxf(pm[row], pm[128 + row]);
                const float mo = msm[row];
                const float mn = fmaxf(mo, tmax);
                mnew[ti][hf] = mn;
                alpha[ti][hf] = __expf(mo - mn);
                float es = 0.f;
#pragma unroll
                for (int tj = 0; tj < 8; tj++) {
                    float e0 = __expf(acc[ti][tj][hf*2]   - mn);
                    float e1 = __expf(acc[ti][tj][hf*2+1] - mn);
                    acc[ti][tj][hf*2]   = e0;
                    acc[ti][tj][hf*2+1] = e1;
                    es += e0 + e1;
                }
                es += __shfl_xor_sync(0xffffffffu, es, 1);
                es += __shfl_xor_sync(0xffffffffu, es, 2);
                if ((lane & 3) == 0) ps[wn*128 + row] = es;
            }
        __syncthreads();

#pragma unroll
        for (int ti = 0; ti < 2; ti++)
#pragma unroll
            for (int hf = 0; hf < 2; hf++) {
                const int row = wm*32 + ti*16 + hf*8 + (lane >> 2);
                if ((lane & 3) == 0 && wn == 0) {
                    const float la = ps[row] + ps[128 + row];
                    lsm[row] = lsm[row]*alpha[ti][hf] + la;
                    msm[row] = mnew[ti][hf];
                    g_mh[(((size_t)bh*16 + rbk)*16 + jt)*128 + row] = mnew[ti][hf];
                }
            }

        // ---- rescale O, write unnormalized P ----
#pragma unroll
        for (int ti = 0; ti < 2; ti++)
#pragma unroll
            for (int nj = 0; nj < 8; nj++) {
                acc_o[ti][nj][0] *= alpha[ti][0];
                acc_o[ti][nj][1] *= alpha[ti][0];
                acc_o[ti][nj][2] *= alpha[ti][1];
                acc_o[ti][nj][3] *= alpha[ti][1];
            }
#pragma unroll
        for (int ti = 0; ti < 2; ti++)
#pragma unroll
            for (int tj = 0; tj < 8; tj++) {
                const int i = i0 + wm*32 + ti*16 + (lane >> 2);
                const int j = jt*128 + wn*64 + tj*8 + (lane & 3)*2;
                *(float2*)&arow[(size_t)i*SS + j]     = make_float2(acc[ti][tj][0], acc[ti][tj][1]);
                *(float2*)&arow[(size_t)(i+8)*SS + j] = make_float2(acc[ti][tj][2], acc[ti][tj][3]);
            }

        // ---- O += P @ V (3-product split, frags from registers) ----
#pragma unroll
        for (int q = 0; q < 4; q++) {
            uint32_t ah[2][4], al[2][4];
#pragma unroll
            for (int ti = 0; ti < 2; ti++) {
                ah[ti][0] = packhl(acc[ti][2*q][0],   acc[ti][2*q][1],   al[ti][0]);
                ah[ti][1] = packhl(acc[ti][2*q][2],   acc[ti][2*q][3],   al[ti][1]);
                ah[ti][2] = packhl(acc[ti][2*q+1][0], acc[ti][2*q+1][1], al[ti][2]);
                ah[ti][3] = packhl(acc[ti][2*q+1][2], acc[ti][2*q+1][3], al[ti][3]);
            }
            const int kb = wn*64 + q*16;
            const uint32_t vrow = (uint32_t)((kb + (lane & 7) + ((lane >> 3) & 1)*8) * VROWB);
            uint32_t Vh[4][4], Vl[4][4];
#pragma unroll
            for (int pj = 0; pj < 4; pj++) {
                const uint32_t voff = vrow + (uint32_t)((pj*16 + ((lane >> 4) & 1)*8) * 2);
                ldsm_x4_t(Vh[pj], smb + FV_H + voff);
                ldsm_x4_t(Vl[pj], smb + FV_L + voff);
            }
#pragma unroll
            for (int ti = 0; ti < 2; ti++)
#pragma unroll
                for (int nj = 0; nj < 8; nj++) {
                    mma_bf16(acc_o[ti][nj], ah[ti], &Vh[nj >> 1][(nj & 1)*2]);
                    mma_bf16(acc_o[ti][nj], al[ti], &Vh[nj >> 1][(nj & 1)*2]);
                    mma_bf16(acc_o[ti][nj], ah[ti], &Vl[nj >> 1][(nj & 1)*2]);
                }
        }
        __syncthreads();
    }

    // final stats to gmem
    if (t < 128) {
        g_mf[(size_t)bh*SS + i0 + t] = msm[t];
        g_ls[(size_t)bh*SS + i0 + t] = lsm[t];
    }

    // O cross-wn reduce + normalize + write ctx
    if (wn == 1) {
#pragma unroll
        for (int ti = 0; ti < 2; ti++)
#pragma unroll
            for (int nj = 0; nj < 8; nj++) {
                const int row0 = wm*32 + ti*16 + (lane >> 2);
                const int cb = nj*8 + (lane & 3)*2;
                *(float2*)(sm + FO_RED + (size_t)row0*256 + cb*4) =
                    make_float2(acc_o[ti][nj][0], acc_o[ti][nj][1]);
                *(float2*)(sm + FO_RED + (size_t)(row0+8)*256 + cb*4) =
                    make_float2(acc_o[ti][nj][2], acc_o[ti][nj][3]);
            }
    }
    __syncthreads();
    if (wn == 0) {
#pragma unroll
        for (int ti = 0; ti < 2; ti++) {
            const int row0 = wm*32 + ti*16 + (lane >> 2);
            const float rl0 = 1.f / lsm[row0];
            const float rl8 = 1.f / lsm[row0 + 8];
#pragma unroll
            for (int nj = 0; nj < 8; nj++) {
                const int cb = nj*8 + (lane & 3)*2;
                float2 p0 = *(float2*)(sm + FO_RED + (size_t)row0*256 + cb*4);
                float2 p8 = *(float2*)(sm + FO_RED + (size_t)(row0+8)*256 + cb*4);
                float2 o0 = make_float2((acc_o[ti][nj][0] + p0.x)*rl0,
                                        (acc_o[ti][nj][1] + p0.y)*rl0);
                float2 o8 = make_float2((acc_o[ti][nj][2] + p8.x)*rl8,
                                        (acc_o[ti][nj][3] + p8.y)*rl8);
                *(float2*)&g_ctx[((size_t)b*SS + i0 + row0)*DD + h*DK + cb] = o0;
                *(float2*)&g_ctx[((size_t)b*SS + i0 + row0 + 8)*DD + h*DK + cb] = o8;
            }
        }
    }
}

// ============================================================
// attn normalization: attn *= exp(m_hist - m_fin) / l
// ============================================================
__global__ void fix_attn(float* __restrict__ attn)
{
    const int blk = blockIdx.x;
    const int bh = blk >> 11, row = blk & 2047;
    const int rbk = row >> 7, rl_ = row & 127;
    const float mfin = g_mf[(size_t)bh*SS + row];
    const float linv = 1.0f / g_ls[(size_t)bh*SS + row];
    const int t = threadIdx.x;
    const size_t base = ((size_t)bh*SS + row)*SS;
    const int c0 = t*4, c1 = 1024 + t*4;
    const float f0 = __expf(g_mh[(((size_t)bh*16 + rbk)*16 + (c0 >> 7))*128 + rl_] - mfin) * linv;
    const float f1 = __expf(g_mh[(((size_t)bh*16 + rbk)*16 + (c1 >> 7))*128 + rl_] - mfin) * linv;
    float4 v0 = *(float4*)(attn + base + c0);
    float4 v1 = *(float4*)(attn + base + c1);
    v0.x *= f0; v0.y *= f0; v0.z *= f0; v0.w *= f0;
    v1.x *= f1; v1.y *= f1; v1.z *= f1; v1.w *= f1;
    *(float4*)(attn + base + c0) = v0;
    *(float4*)(attn + base + c1) = v1;
}

// ============================================================
// out = LayerNorm(pre + residual)
// ============================================================
__global__ void ln_kernel(const float* __restrict__ resid,
                          float* __restrict__ out)
{
    const size_t base = (size_t)blockIdx.x * DD;
    const int t = threadIdx.x;
    __shared__ float red1[8];
    __shared__ float red2[8];

    float v[4];
    float s = 0.f;
#pragma unroll
    for (int j = 0; j < 4; j++) {
        v[j] = g_pre[base + t + 256*j] + resid[base + t + 256*j];
        s += v[j];
    }
#pragma unroll
    for (int o = 16; o > 0; o >>= 1) s += __shfl_xor_sync(0xffffffffu, s, o);
    if ((t & 31) == 0) red1[t >> 5] = s;
    __syncthreads();
    s = red1[0];
#pragma unroll
    for (int w = 1; w < 8; w++) s += red1[w];
    const float mu = s * (1.0f / DD);

    float sq = 0.f;
#pragma unroll
    for (int j = 0; j < 4; j++) { const float d = v[j] - mu; sq += d*d; }
#pragma unroll
    for (int o = 16; o > 0; o >>= 1) sq += __shfl_xor_sync(0xffffffffu, sq, o);
    if ((t & 31) == 0) red2[t >> 5] = sq;
    __syncthreads();
    sq = red2[0];
#pragma unroll
    for (int w = 1; w < 8; w++) sq += red2[w];
    const float inv = rsqrtf(sq * (1.0f / DD) + 1e-5f);

#pragma unroll
    for (int j = 0; j < 4; j++) out[base + t + 256*j] = (v[j] - mu) * inv;
}

// ============================================================
extern "C" void kernel_launch(void* const* d_in, const int* in_sizes, int n_in,
                              void* d_out, int out_size)
{
    const float* inQ  = (const float*)d_in[0];
    const float* inK  = (const float*)d_in[1];
    const float* inV  = (const float*)d_in[2];
    const int*   mask = (const int*)  d_in[3];
    const float* WQ   = (const float*)d_in[4];
    const float* WK   = (const float*)d_in[5];
    const float* WV   = (const float*)d_in[6];
    const float* Wfc  = (const float*)d_in[7];
    float* out = (float*)d_out;

    float *pQ, *pK, *pV, *pctx, *ppre, *psc, *pdmy;
    cudaGetSymbolAddress((void**)&pQ,   g_Q);
    cudaGetSymbolAddress((void**)&pK,   g_K);
    cudaGetSymbolAddress((void**)&pV,   g_V);
    cudaGetSymbolAddress((void**)&pctx, g_ctx);
    cudaGetSymbolAddress((void**)&ppre, g_pre);
    cudaGetSymbolAddress((void**)&psc,  g_scores);
    cudaGetSymbolAddress((void**)&pdmy, g_dummy_out);

    const long long OUT_E  = (long long)NT * DD;
    const long long ATTN_E = (long long)BB * HH * SS * SS;

    float* out_dst  = out;
    float* attn_dst = psc;
    if ((long long)out_size >= OUT_E + ATTN_E) {
        attn_dst = out + OUT_E;
    } else if ((long long)out_size == ATTN_E) {
        attn_dst = out;
        out_dst  = pdmy;
    }

    static int smem_set = 0;
    if (!smem_set) {
        cudaFuncSetAttribute(flash_attn, cudaFuncAttributeMaxDynamicSharedMemorySize, DYNSM_F);
        smem_set = 1;
    }

    const dim3 blk(256);

    // projections on warp-MMA (bf16 hi/lo split, fp32-class accuracy)
    gemm_mma<<<dim3(DD/128, NT/128), blk, DYNSM>>>(inQ, WQ, pQ, DD, DD);
    gemm_mma<<<dim3(DD/128, NT/128), blk, DYNSM>>>(inK, WK, pK, DD, DD);
    gemm_mma<<<dim3(DD/128, NT/128), blk, DYNSM>>>(inV, WV, pV, DD, DD);

    // fused attention: S, online softmax, unnormalized P write, O = P@V
    flash_attn<<<dim3(16, BB*HH), blk, DYNSM_F>>>(mask, attn_dst);

    // normalize attn in-place
    fix_attn<<<(unsigned)(BB*HH*SS), blk>>>(attn_dst);

    // output projection
    gemm_mma<<<dim3(DD/128, NT/128), blk, DYNSM>>>(pctx, Wfc, ppre, DD, DD);

    // residual + layernorm
    ln_kernel<<<(unsigned)NT, blk>>>(inQ, out_dst);
}